// round 8
// baseline (speedup 1.0000x reference)
#include <cuda_runtime.h>
#include <cuda_bf16.h>
#include <stdint.h>
#include <math.h>

// ---------------- problem constants ----------------
#define NN 50000
#define EE 800000
#define IND 256
#define HD 128      // hidden = out = heads*c1 = 128
#define NHEADS 8
#define C1 16
#define SCAN_BLK 256
#define NSCAN ((NN + SCAN_BLK - 1) / SCAN_BLK)   // 196
#define AK 24       // smem bf16 row stride (48B: conflict-free frag loads)

// ---------------- scratch (static device memory; no allocs) ----------------
__device__ __align__(16) float g_h0[NN * HD];
__device__ __align__(16) float g_t1[NN * HD];
__device__ __align__(16) float g_out1[NN * HD];
__device__ __align__(16) float g_t2[NN * HD];
__device__ __align__(16) float g_conv2[NN * HD];
__device__ __align__(16) float g_h2[NN * HD];
__device__ __align__(16) float g_alpha1[(size_t)EE * NHEADS];
__device__ __align__(16) float g_alpha2[EE];
__device__ __align__(16) float g_as1[NN * NHEADS], g_ad1[NN * NHEADS];
__device__ __align__(16) float g_as2[NN], g_ad2[NN];
__device__ __align__(16) int   g_cnt[NN];
__device__ __align__(16) int   g_scantmp[NN];
__device__ __align__(16) int   g_blksum[SCAN_BLK];
__device__ __align__(16) int   g_blkoff[SCAN_BLK];
__device__ int   g_total;
__device__ __align__(16) int   g_rowptr[NN + 1];
__device__ __align__(16) int   g_cursor[NN];
__device__ __align__(16) int   g_csrc[EE];
__device__ __align__(16) float g_bnsum1[HD], g_bnsq1[HD], g_bnsum2[HD], g_bnsq2[HD];
__device__ __align__(16) float g_scale1[HD], g_shift1[HD];
__device__ __align__(16) float g_W1p[HD * HD], g_c1[HD];
__device__ __align__(16) float g_s2[HD], g_sh2[HD];
__device__ int g_is64;

__device__ __forceinline__ float lrelu(float v) { return v >= 0.f ? v : 0.2f * v; }

__device__ __forceinline__ int edge_idx(const void* ei, long long pos) {
    if (g_is64) return (int)((const long long*)ei)[pos];
    return ((const int*)ei)[pos];
}

// ---------------- dtype detection ----------------
__global__ void k_detect(const void* ei) {
    const long long* q = (const long long*)ei;
    int ok = 1;
    for (int i = 0; i < 64; i++) {
        long long v = q[i];
        if (v < 0 || v >= NN) { ok = 0; break; }
    }
    g_is64 = ok;
}

// ---------------- zero ----------------
__global__ void k_zero() {
    int i = blockIdx.x * blockDim.x + threadIdx.x;
    if (i < NN) g_cnt[i] = 0;
    if (i < HD) { g_bnsum1[i] = 0.f; g_bnsq1[i] = 0.f; g_bnsum2[i] = 0.f; g_bnsq2[i] = 0.f; }
}

// ---------------- CSR build ----------------
__global__ void k_count(const void* __restrict__ ei) {
    int e = blockIdx.x * blockDim.x + threadIdx.x;
    if (e < EE) {
        int d = edge_idx(ei, (long long)EE + e);
        if (d >= 0 && d < NN) atomicAdd(&g_cnt[d], 1);
    }
}

__global__ void k_scanA() {
    __shared__ int sh[SCAN_BLK];
    int tid = threadIdx.x;
    int i = blockIdx.x * SCAN_BLK + tid;
    int v = (i < NN) ? g_cnt[i] : 0;
    sh[tid] = v;
    __syncthreads();
#pragma unroll
    for (int off = 1; off < SCAN_BLK; off <<= 1) {
        int t = (tid >= off) ? sh[tid - off] : 0;
        __syncthreads();
        sh[tid] += t;
        __syncthreads();
    }
    if (i < NN) g_scantmp[i] = sh[tid];
    if (tid == SCAN_BLK - 1) g_blksum[blockIdx.x] = sh[tid];
}

__global__ void k_scanB() {
    __shared__ int sh[SCAN_BLK];
    int tid = threadIdx.x;
    int v = (tid < NSCAN) ? g_blksum[tid] : 0;
    sh[tid] = v;
    __syncthreads();
#pragma unroll
    for (int off = 1; off < SCAN_BLK; off <<= 1) {
        int t = (tid >= off) ? sh[tid - off] : 0;
        __syncthreads();
        sh[tid] += t;
        __syncthreads();
    }
    g_blkoff[tid] = sh[tid] - v;
    if (tid == SCAN_BLK - 1) g_total = sh[tid];
}

__global__ void k_scanC() {
    int i = blockIdx.x * blockDim.x + threadIdx.x;
    if (i < NN) {
        int r = g_blkoff[blockIdx.x] + g_scantmp[i] - g_cnt[i];
        g_rowptr[i] = r;
        g_cursor[i] = r;
    }
    if (i == 0) g_rowptr[NN] = g_total;
}

__global__ void k_fill(const void* __restrict__ ei) {
    int e = blockIdx.x * blockDim.x + threadIdx.x;
    if (e < EE) {
        int s = edge_idx(ei, e);
        int d = edge_idx(ei, (long long)EE + e);
        if (d >= 0 && d < NN && s >= 0 && s < NN) {
            int p = atomicAdd(&g_cursor[d], 1);
            if (p >= 0 && p < EE) g_csrc[p] = s;
        }
    }
}

// ---------------- split-bf16 tensor-core GEMM ----------------
// C[NN,128] = A[NN,K] @ B[K,128] in ~fp32 precision via 3-term bf16 split:
// A = Ah+Al, B = Bh+Bl; C ≈ Ah*Bh + Ah*Bl + Al*Bh  (err ~2^-16)
__device__ __forceinline__ void mma16816(float* c, const uint32_t* a, uint32_t b0, uint32_t b1) {
    asm volatile(
        "mma.sync.aligned.m16n8k16.row.col.f32.bf16.bf16.f32 "
        "{%0,%1,%2,%3}, {%4,%5,%6,%7}, {%8,%9}, {%0,%1,%2,%3};"
        : "+f"(c[0]), "+f"(c[1]), "+f"(c[2]), "+f"(c[3])
        : "r"(a[0]), "r"(a[1]), "r"(a[2]), "r"(a[3]), "r"(b0), "r"(b1));
}

template <int K, bool LEAKY, bool ADDM, bool STATS>
__global__ void __launch_bounds__(256, 2) k_gemm_tc(
        const float* __restrict__ A, const float* __restrict__ B,
        float* __restrict__ C, const float* __restrict__ bias,
        const float* __restrict__ addm,
        float* __restrict__ bnsum, float* __restrict__ bnsq) {
    __shared__ __nv_bfloat16 Ah[128 * AK], Al[128 * AK];
    __shared__ __nv_bfloat16 Bh[128 * AK], Bl[128 * AK];   // B transposed: [n][k]
    __shared__ float s_sum[128], s_sq[128];
    const int tid = threadIdx.x;
    const int m0 = blockIdx.x * 128;
    if (STATS && tid < 128) { s_sum[tid] = 0.f; s_sq[tid] = 0.f; }
    const int lane = tid & 31;
    const int wid = tid >> 5;
    const int g = lane >> 2, r = lane & 3;
    const int wm = (wid & 3) * 32;     // warp m offset in tile
    const int wn = (wid >> 2) * 64;    // warp n offset in tile

    float acc[2][8][4];
#pragma unroll
    for (int i = 0; i < 2; i++)
#pragma unroll
        for (int j = 0; j < 8; j++)
#pragma unroll
            for (int q = 0; q < 4; q++) acc[i][j][q] = 0.f;

    const int arow = tid >> 1;          // 0..127
    const int akof = (tid & 1) * 8;     // 0 or 8
    const int bk   = tid >> 4;          // 0..15
    const int bn   = (tid & 15) * 8;    // 0..120

    for (int k0 = 0; k0 < K; k0 += 16) {
        // ---- A tile 128x16 -> hi/lo bf16 ----
        {
            float af[8];
            if (m0 + arow < NN) {
                const float* ap = A + (size_t)(m0 + arow) * K + k0 + akof;
                float4 v0 = *(const float4*)ap, v1 = *(const float4*)(ap + 4);
                af[0]=v0.x; af[1]=v0.y; af[2]=v0.z; af[3]=v0.w;
                af[4]=v1.x; af[5]=v1.y; af[6]=v1.z; af[7]=v1.w;
            } else {
#pragma unroll
                for (int i = 0; i < 8; i++) af[i] = 0.f;
            }
#pragma unroll
            for (int i = 0; i < 8; i++) {
                __nv_bfloat16 h = __float2bfloat16(af[i]);
                Ah[arow * AK + akof + i] = h;
                Al[arow * AK + akof + i] = __float2bfloat16(af[i] - __bfloat162float(h));
            }
        }
        // ---- B tile 16x128 -> transposed hi/lo bf16 ----
        {
            const float* bp = B + (size_t)(k0 + bk) * HD + bn;
            float4 v0 = *(const float4*)bp, v1 = *(const float4*)(bp + 4);
            float bf[8] = {v0.x, v0.y, v0.z, v0.w, v1.x, v1.y, v1.z, v1.w};
#pragma unroll
            for (int i = 0; i < 8; i++) {
                __nv_bfloat16 h = __float2bfloat16(bf[i]);
                Bh[(bn + i) * AK + bk] = h;
                Bl[(bn + i) * AK + bk] = __float2bfloat16(bf[i] - __bfloat162float(h));
            }
        }
        __syncthreads();

        // ---- A fragments (2 m-frags, hi+lo) ----
        uint32_t ah[2][4], al[2][4];
#pragma unroll
        for (int mi = 0; mi < 2; mi++) {
            int mr = wm + mi * 16;
            ah[mi][0] = *(const uint32_t*)&Ah[(mr + g) * AK + 2 * r];
            ah[mi][1] = *(const uint32_t*)&Ah[(mr + g + 8) * AK + 2 * r];
            ah[mi][2] = *(const uint32_t*)&Ah[(mr + g) * AK + 2 * r + 8];
            ah[mi][3] = *(const uint32_t*)&Ah[(mr + g + 8) * AK + 2 * r + 8];
            al[mi][0] = *(const uint32_t*)&Al[(mr + g) * AK + 2 * r];
            al[mi][1] = *(const uint32_t*)&Al[(mr + g + 8) * AK + 2 * r];
            al[mi][2] = *(const uint32_t*)&Al[(mr + g) * AK + 2 * r + 8];
            al[mi][3] = *(const uint32_t*)&Al[(mr + g + 8) * AK + 2 * r + 8];
        }
#pragma unroll
        for (int ni = 0; ni < 8; ni++) {
            int nr = (wn + ni * 8 + g) * AK;
            uint32_t bh0 = *(const uint32_t*)&Bh[nr + 2 * r];
            uint32_t bh1 = *(const uint32_t*)&Bh[nr + 2 * r + 8];
            uint32_t bl0 = *(const uint32_t*)&Bl[nr + 2 * r];
            uint32_t bl1 = *(const uint32_t*)&Bl[nr + 2 * r + 8];
#pragma unroll
            for (int mi = 0; mi < 2; mi++) {
                mma16816(acc[mi][ni], al[mi], bh0, bh1);   // lo*hi
                mma16816(acc[mi][ni], ah[mi], bl0, bl1);   // hi*lo
                mma16816(acc[mi][ni], ah[mi], bh0, bh1);   // hi*hi
            }
        }
        __syncthreads();
    }

    // ---- epilogue ----
#pragma unroll
    for (int mi = 0; mi < 2; mi++) {
#pragma unroll
        for (int ni = 0; ni < 8; ni++) {
            int mA = m0 + wm + mi * 16 + g;
            int mB = mA + 8;
            int n = wn + ni * 8 + 2 * r;
            float bc0 = bias ? bias[n] : 0.f;
            float bc1 = bias ? bias[n + 1] : 0.f;
            float v0 = acc[mi][ni][0] + bc0, v1 = acc[mi][ni][1] + bc1;
            float v2 = acc[mi][ni][2] + bc0, v3 = acc[mi][ni][3] + bc1;
            bool okA = mA < NN, okB = mB < NN;
            if (okA) {
                if (ADDM) { v0 += addm[(size_t)mA * HD + n]; v1 += addm[(size_t)mA * HD + n + 1]; }
                if (LEAKY) { v0 = lrelu(v0); v1 = lrelu(v1); }
                *(float2*)&C[(size_t)mA * HD + n] = make_float2(v0, v1);
            }
            if (okB) {
                if (ADDM) { v2 += addm[(size_t)mB * HD + n]; v3 += addm[(size_t)mB * HD + n + 1]; }
                if (LEAKY) { v2 = lrelu(v2); v3 = lrelu(v3); }
                *(float2*)&C[(size_t)mB * HD + n] = make_float2(v2, v3);
            }
            if (STATS) {
                float s0 = (okA ? v0 : 0.f) + (okB ? v2 : 0.f);
                float s1 = (okA ? v1 : 0.f) + (okB ? v3 : 0.f);
                float q0 = (okA ? v0 * v0 : 0.f) + (okB ? v2 * v2 : 0.f);
                float q1 = (okA ? v1 * v1 : 0.f) + (okB ? v3 * v3 : 0.f);
                if (okA || okB) {
                    atomicAdd(&s_sum[n], s0);
                    atomicAdd(&s_sum[n + 1], s1);
                    atomicAdd(&s_sq[n], q0);
                    atomicAdd(&s_sq[n + 1], q1);
                }
            }
        }
    }
    if (STATS) {
        __syncthreads();
        if (tid < 128) {
            atomicAdd(&bnsum[tid], s_sum[tid]);
            atomicAdd(&bnsq[tid], s_sq[tid]);
        }
    }
}

// ---------------- BN preps ----------------
__global__ void k_bnprep1(const float* __restrict__ gamma1, const float* __restrict__ beta1,
                          const float* __restrict__ W1) {
    int c = threadIdx.x;
    float mean = g_bnsum1[c] / (float)NN;
    float var = g_bnsq1[c] / (float)NN - mean * mean;
    float sc = gamma1[c] * rsqrtf(var + 1e-5f);
    float sh = beta1[c] - mean * sc;
    g_scale1[c] = sc;
    g_shift1[c] = sh;
    __syncthreads();
    float cj = 0.f;
    for (int k = 0; k < HD; k++) {
        cj += g_shift1[k] * W1[k * HD + c];
        g_W1p[k * HD + c] = g_scale1[k] * W1[k * HD + c];
    }
    g_c1[c] = cj;
}

__global__ void k_bnprep2(const float* __restrict__ gamma2, const float* __restrict__ beta2) {
    int c = threadIdx.x;
    float mean = g_bnsum2[c] / (float)NN;
    float var = g_bnsq2[c] / (float)NN - mean * mean;
    float sc = gamma2[c] * rsqrtf(var + 1e-5f);
    g_s2[c] = sc;
    g_sh2[c] = beta2[c] - mean * sc;
}

// ---------------- attention coefficients ----------------
__global__ void k_att1(const float* __restrict__ att_src, const float* __restrict__ att_dst) {
    int gt = blockIdx.x * blockDim.x + threadIdx.x;
    int w = gt >> 5, lane = gt & 31;
    if (w >= NN) return;
    float4 t4 = *reinterpret_cast<const float4*>(g_t1 + (size_t)w * HD + lane * 4);
    float4 s4 = *reinterpret_cast<const float4*>(att_src + lane * 4);
    float4 d4 = *reinterpret_cast<const float4*>(att_dst + lane * 4);
    float ps = t4.x * s4.x + t4.y * s4.y + t4.z * s4.z + t4.w * s4.w;
    float pd = t4.x * d4.x + t4.y * d4.y + t4.z * d4.z + t4.w * d4.w;
    ps += __shfl_xor_sync(0xFFFFFFFFu, ps, 1); ps += __shfl_xor_sync(0xFFFFFFFFu, ps, 2);
    pd += __shfl_xor_sync(0xFFFFFFFFu, pd, 1); pd += __shfl_xor_sync(0xFFFFFFFFu, pd, 2);
    if ((lane & 3) == 0) {
        g_as1[w * NHEADS + (lane >> 2)] = ps;
        g_ad1[w * NHEADS + (lane >> 2)] = pd;
    }
}

__global__ void k_att2(const float* __restrict__ att_src, const float* __restrict__ att_dst) {
    int gt = blockIdx.x * blockDim.x + threadIdx.x;
    int w = gt >> 5, lane = gt & 31;
    if (w >= NN) return;
    float4 t4 = *reinterpret_cast<const float4*>(g_t2 + (size_t)w * HD + lane * 4);
    float4 s4 = *reinterpret_cast<const float4*>(att_src + lane * 4);
    float4 d4 = *reinterpret_cast<const float4*>(att_dst + lane * 4);
    float ps = t4.x * s4.x + t4.y * s4.y + t4.z * s4.z + t4.w * s4.w;
    float pd = t4.x * d4.x + t4.y * d4.y + t4.z * d4.z + t4.w * d4.w;
#pragma unroll
    for (int off = 16; off; off >>= 1) {
        ps += __shfl_xor_sync(0xFFFFFFFFu, ps, off);
        pd += __shfl_xor_sync(0xFFFFFFFFu, pd, off);
    }
    if (lane == 0) { g_as2[w] = ps; g_ad2[w] = pd; }
}

// ---------------- softmax per dst ----------------
__global__ void k_softmax1() {
    int gt = blockIdx.x * blockDim.x + threadIdx.x;
    int w = gt >> 5, lane = gt & 31;
    if (w >= NN) return;
    int beg = g_rowptr[w], end = g_rowptr[w + 1];
    if (beg == end) return;
    int h = lane & 7, es = lane >> 3;
    float ad = g_ad1[w * NHEADS + h];
    float mx = -INFINITY;
    for (int j = beg + es; j < end; j += 4) {
        int s = g_csrc[j];
        float v = lrelu(g_as1[s * NHEADS + h] + ad);
        mx = fmaxf(mx, v);
    }
    mx = fmaxf(mx, __shfl_xor_sync(0xFFFFFFFFu, mx, 8));
    mx = fmaxf(mx, __shfl_xor_sync(0xFFFFFFFFu, mx, 16));
    float den = 0.f;
    for (int j = beg + es; j < end; j += 4) {
        int s = g_csrc[j];
        float v = lrelu(g_as1[s * NHEADS + h] + ad);
        den += __expf(v - mx);
    }
    den += __shfl_xor_sync(0xFFFFFFFFu, den, 8);
    den += __shfl_xor_sync(0xFFFFFFFFu, den, 16);
    float inv = 1.f / fmaxf(den, 1e-16f);
    for (int j = beg + es; j < end; j += 4) {
        int s = g_csrc[j];
        float v = lrelu(g_as1[s * NHEADS + h] + ad);
        g_alpha1[(size_t)j * NHEADS + h] = __expf(v - mx) * inv;
    }
}

__global__ void k_softmax2() {
    int gt = blockIdx.x * blockDim.x + threadIdx.x;
    int w = gt >> 5, lane = gt & 31;
    if (w >= NN) return;
    int beg = g_rowptr[w], end = g_rowptr[w + 1];
    if (beg == end) return;
    float ad = g_ad2[w];
    float mx = -INFINITY;
    for (int j = beg + lane; j < end; j += 32) {
        float v = lrelu(g_as2[g_csrc[j]] + ad);
        mx = fmaxf(mx, v);
    }
#pragma unroll
    for (int off = 16; off; off >>= 1) mx = fmaxf(mx, __shfl_xor_sync(0xFFFFFFFFu, mx, off));
    float den = 0.f;
    for (int j = beg + lane; j < end; j += 32) {
        float v = lrelu(g_as2[g_csrc[j]] + ad);
        den += __expf(v - mx);
    }
#pragma unroll
    for (int off = 16; off; off >>= 1) den += __shfl_xor_sync(0xFFFFFFFFu, den, off);
    float inv = 1.f / fmaxf(den, 1e-16f);
    for (int j = beg + lane; j < end; j += 32) {
        float v = lrelu(g_as2[g_csrc[j]] + ad);
        g_alpha2[j] = __expf(v - mx) * inv;
    }
}

// ---------------- aggregation ----------------
__global__ void k_agg1(const float* __restrict__ bias1) {
    int gt = blockIdx.x * blockDim.x + threadIdx.x;
    int w = gt >> 5, lane = gt & 31;
    if (w >= NN) return;
    int beg = g_rowptr[w], end = g_rowptr[w + 1];
    int hh = lane >> 2;
    float ax = 0.f, ay = 0.f, az = 0.f, aw = 0.f;
#pragma unroll 2
    for (int j = beg; j < end; j++) {
        int s = g_csrc[j];
        float a = g_alpha1[(size_t)j * NHEADS + hh];
        float4 t4 = *reinterpret_cast<const float4*>(g_t1 + (size_t)s * HD + lane * 4);
        ax += a * t4.x; ay += a * t4.y; az += a * t4.z; aw += a * t4.w;
    }
    float4 b4 = *reinterpret_cast<const float4*>(bias1 + lane * 4);
    float4 o;
    o.x = lrelu(ax + b4.x); o.y = lrelu(ay + b4.y);
    o.z = lrelu(az + b4.z); o.w = lrelu(aw + b4.w);
    *reinterpret_cast<float4*>(g_out1 + (size_t)w * HD + lane * 4) = o;
}

__global__ void k_agg2(const float* __restrict__ bias2) {
    int gt = blockIdx.x * blockDim.x + threadIdx.x;
    int w = gt >> 5, lane = gt & 31;
    if (w >= NN) return;
    int beg = g_rowptr[w], end = g_rowptr[w + 1];
    float ax = 0.f, ay = 0.f, az = 0.f, aw = 0.f;
#pragma unroll 2
    for (int j = beg; j < end; j++) {
        int s = g_csrc[j];
        float a = g_alpha2[j];
        float4 t4 = *reinterpret_cast<const float4*>(g_t2 + (size_t)s * HD + lane * 4);
        ax += a * t4.x; ay += a * t4.y; az += a * t4.z; aw += a * t4.w;
    }
    float4 b4 = *reinterpret_cast<const float4*>(bias2 + lane * 4);
    float4 o = make_float4(ax + b4.x, ay + b4.y, az + b4.z, aw + b4.w);
    *reinterpret_cast<float4*>(g_conv2 + (size_t)w * HD + lane * 4) = o;
}

// ---------------- final: BN2 apply + row L2 normalize ----------------
__global__ void k_final(float* __restrict__ out) {
    int gt = blockIdx.x * blockDim.x + threadIdx.x;
    int w = gt >> 5, lane = gt & 31;
    if (w >= NN) return;
    float4 h4 = *reinterpret_cast<const float4*>(g_h2 + (size_t)w * HD + lane * 4);
    float4 s4 = *reinterpret_cast<const float4*>(g_s2 + lane * 4);
    float4 sh4 = *reinterpret_cast<const float4*>(g_sh2 + lane * 4);
    float4 y;
    y.x = h4.x * s4.x + sh4.x; y.y = h4.y * s4.y + sh4.y;
    y.z = h4.z * s4.z + sh4.z; y.w = h4.w * s4.w + sh4.w;
    float ss = y.x * y.x + y.y * y.y + y.z * y.z + y.w * y.w;
#pragma unroll
    for (int off = 16; off; off >>= 1) ss += __shfl_xor_sync(0xFFFFFFFFu, ss, off);
    float inv = 1.f / fmaxf(sqrtf(ss), 1e-12f);
    y.x *= inv; y.y *= inv; y.z *= inv; y.w *= inv;
    *reinterpret_cast<float4*>(out + (size_t)w * HD + lane * 4) = y;
}

// ---------------- host launcher ----------------
extern "C" void kernel_launch(void* const* d_in, const int* in_sizes, int n_in,
                              void* d_out, int out_size) {
    const float* x        = (const float*)d_in[0];
    const float* W_in     = (const float*)d_in[1];
    const float* b_in     = (const float*)d_in[2];
    const float* gamma1   = (const float*)d_in[3];
    const float* beta1    = (const float*)d_in[4];
    const float* W1       = (const float*)d_in[5];
    const float* att_src1 = (const float*)d_in[6];
    const float* att_dst1 = (const float*)d_in[7];
    const float* bias1    = (const float*)d_in[8];
    const float* W2       = (const float*)d_in[9];
    const float* att_src2 = (const float*)d_in[10];
    const float* att_dst2 = (const float*)d_in[11];
    const float* bias2    = (const float*)d_in[12];
    const float* W_skip   = (const float*)d_in[13];
    const float* b_skip   = (const float*)d_in[14];
    const float* gamma2   = (const float*)d_in[15];
    const float* beta2    = (const float*)d_in[16];
    const void*  ei       = (const void*)d_in[17];
    float* out = (float*)d_out;

    float *p_h0, *p_t1, *p_out1, *p_t2, *p_conv2, *p_h2, *p_W1p, *p_c1;
    float *p_bnsum1, *p_bnsq1, *p_bnsum2, *p_bnsq2;
    cudaGetSymbolAddress((void**)&p_h0, g_h0);
    cudaGetSymbolAddress((void**)&p_t1, g_t1);
    cudaGetSymbolAddress((void**)&p_out1, g_out1);
    cudaGetSymbolAddress((void**)&p_t2, g_t2);
    cudaGetSymbolAddress((void**)&p_conv2, g_conv2);
    cudaGetSymbolAddress((void**)&p_h2, g_h2);
    cudaGetSymbolAddress((void**)&p_W1p, g_W1p);
    cudaGetSymbolAddress((void**)&p_c1, g_c1);
    cudaGetSymbolAddress((void**)&p_bnsum1, g_bnsum1);
    cudaGetSymbolAddress((void**)&p_bnsq1, g_bnsq1);
    cudaGetSymbolAddress((void**)&p_bnsum2, g_bnsum2);
    cudaGetSymbolAddress((void**)&p_bnsq2, g_bnsq2);

    const int nb_edge = (EE + 255) / 256;
    const int nb_node = (NN * 32 + 255) / 256;
    const int gemm_grid = (NN + 127) / 128;

    k_detect<<<1, 1>>>(ei);
    k_zero<<<(NN + 255) / 256, 256>>>();
    k_count<<<nb_edge, 256>>>(ei);
    k_scanA<<<NSCAN, SCAN_BLK>>>();
    k_scanB<<<1, SCAN_BLK>>>();
    k_scanC<<<NSCAN, SCAN_BLK>>>();
    k_fill<<<nb_edge, 256>>>(ei);

    // h0 = leaky(x @ W_in + b_in), BN1 stats
    k_gemm_tc<IND, true, false, true><<<gemm_grid, 256>>>(x, W_in, p_h0, b_in, nullptr, p_bnsum1, p_bnsq1);
    k_bnprep1<<<1, HD>>>(gamma1, beta1, W1);
    // t1 = h_norm @ W1  (BN folded)
    k_gemm_tc<HD, false, false, false><<<gemm_grid, 256>>>(p_h0, p_W1p, p_t1, p_c1, nullptr, nullptr, nullptr);
    k_att1<<<nb_node, 256>>>(att_src1, att_dst1);
    k_softmax1<<<nb_node, 256>>>();
    k_agg1<<<nb_node, 256>>>(bias1);
    // t2 = out1 @ W2
    k_gemm_tc<HD, false, false, false><<<gemm_grid, 256>>>(p_out1, W2, p_t2, nullptr, nullptr, nullptr, nullptr);
    k_att2<<<nb_node, 256>>>(att_src2, att_dst2);
    k_softmax2<<<nb_node, 256>>>();
    k_agg2<<<nb_node, 256>>>(bias2);
    // h2 = conv2 + out1 @ W_skip + b_skip, BN2 stats
    k_gemm_tc<HD, false, true, true><<<gemm_grid, 256>>>(p_out1, W_skip, p_h2, b_skip, p_conv2, p_bnsum2, p_bnsq2);
    k_bnprep2<<<1, HD>>>(gamma2, beta2);
    k_final<<<nb_node, 256>>>(out);
}

// round 9
// speedup vs baseline: 1.2900x; 1.2900x over previous
#include <cuda_runtime.h>
#include <cuda_bf16.h>
#include <stdint.h>
#include <math.h>

// ---------------- problem constants ----------------
#define NN 50000
#define EE 800000
#define IND 256
#define HD 128
#define NHEADS 8
#define SCAN_BLK 256
#define NSCAN ((NN + SCAN_BLK - 1) / SCAN_BLK)
#define AK 24   // smem bf16 row stride (48B)

// ---------------- scratch ----------------
__device__ __align__(16) __nv_bfloat16 g_xh[(size_t)NN * IND], g_xl[(size_t)NN * IND];
__device__ __align__(16) __nv_bfloat16 g_h0h[NN * HD], g_h0l[NN * HD];
__device__ __align__(16) __nv_bfloat16 g_o1h[NN * HD], g_o1l[NN * HD];
__device__ __align__(16) __nv_bfloat16 g_Winth[HD * IND], g_Wintl[HD * IND];   // W_in^T hi/lo [128][256]
__device__ __align__(16) __nv_bfloat16 g_W1th[HD * HD], g_W1tl[HD * HD];
__device__ __align__(16) __nv_bfloat16 g_W2th[HD * HD], g_W2tl[HD * HD];
__device__ __align__(16) __nv_bfloat16 g_Wsth[HD * HD], g_Wstl[HD * HD];
__device__ __align__(16) float g_t1[NN * HD];
__device__ __align__(16) float g_t2[NN * HD];
__device__ __align__(16) float g_conv2[NN * HD];
__device__ __align__(16) float g_h2[NN * HD];
__device__ __align__(16) float g_alpha1[(size_t)EE * NHEADS];
__device__ __align__(16) float g_alpha2[EE];
__device__ __align__(16) float g_as1[NN * NHEADS], g_ad1[NN * NHEADS];
__device__ __align__(16) float g_as2[NN], g_ad2[NN];
__device__ __align__(16) int   g_cnt[NN];
__device__ __align__(16) int   g_scantmp[NN];
__device__ __align__(16) int   g_blksum[SCAN_BLK];
__device__ __align__(16) int   g_blkoff[SCAN_BLK];
__device__ int   g_total;
__device__ __align__(16) int   g_rowptr[NN + 1];
__device__ __align__(16) int   g_cursor[NN];
__device__ __align__(16) int   g_csrc[EE];
__device__ __align__(16) float g_bnsum1[HD], g_bnsq1[HD], g_bnsum2[HD], g_bnsq2[HD];
__device__ __align__(16) float g_scale1[HD], g_shift1[HD];
__device__ __align__(16) float g_W1p[HD * HD], g_c1[HD];
__device__ __align__(16) float g_s2[HD], g_sh2[HD];
__device__ int g_is64;

__device__ __forceinline__ float lrelu(float v) { return v >= 0.f ? v : 0.2f * v; }

__device__ __forceinline__ int edge_idx(const void* ei, long long pos) {
    if (g_is64) return (int)((const long long*)ei)[pos];
    return ((const int*)ei)[pos];
}

// ---------------- dtype detection ----------------
__global__ void k_detect(const void* ei) {
    const long long* q = (const long long*)ei;
    int ok = 1;
    for (int i = 0; i < 64; i++) {
        long long v = q[i];
        if (v < 0 || v >= NN) { ok = 0; break; }
    }
    g_is64 = ok;
}

// ---------------- zero ----------------
__global__ void k_zero() {
    int i = blockIdx.x * blockDim.x + threadIdx.x;
    if (i < NN) g_cnt[i] = 0;
    if (i < HD) { g_bnsum1[i] = 0.f; g_bnsq1[i] = 0.f; g_bnsum2[i] = 0.f; g_bnsq2[i] = 0.f; }
}

// ---------------- CSR build ----------------
__global__ void k_count(const void* __restrict__ ei) {
    int e = blockIdx.x * blockDim.x + threadIdx.x;
    if (e < EE) {
        int d = edge_idx(ei, (long long)EE + e);
        if (d >= 0 && d < NN) atomicAdd(&g_cnt[d], 1);
    }
}

__global__ void k_scanA() {
    __shared__ int sh[SCAN_BLK];
    int tid = threadIdx.x;
    int i = blockIdx.x * SCAN_BLK + tid;
    int v = (i < NN) ? g_cnt[i] : 0;
    sh[tid] = v;
    __syncthreads();
#pragma unroll
    for (int off = 1; off < SCAN_BLK; off <<= 1) {
        int t = (tid >= off) ? sh[tid - off] : 0;
        __syncthreads();
        sh[tid] += t;
        __syncthreads();
    }
    if (i < NN) g_scantmp[i] = sh[tid];
    if (tid == SCAN_BLK - 1) g_blksum[blockIdx.x] = sh[tid];
}

__global__ void k_scanB() {
    __shared__ int sh[SCAN_BLK];
    int tid = threadIdx.x;
    int v = (tid < NSCAN) ? g_blksum[tid] : 0;
    sh[tid] = v;
    __syncthreads();
#pragma unroll
    for (int off = 1; off < SCAN_BLK; off <<= 1) {
        int t = (tid >= off) ? sh[tid - off] : 0;
        __syncthreads();
        sh[tid] += t;
        __syncthreads();
    }
    g_blkoff[tid] = sh[tid] - v;
    if (tid == SCAN_BLK - 1) g_total = sh[tid];
}

__global__ void k_scanC() {
    int i = blockIdx.x * blockDim.x + threadIdx.x;
    if (i < NN) {
        int r = g_blkoff[blockIdx.x] + g_scantmp[i] - g_cnt[i];
        g_rowptr[i] = r;
        g_cursor[i] = r;
    }
    if (i == 0) g_rowptr[NN] = g_total;
}

__global__ void k_fill(const void* __restrict__ ei) {
    int e = blockIdx.x * blockDim.x + threadIdx.x;
    if (e < EE) {
        int s = edge_idx(ei, e);
        int d = edge_idx(ei, (long long)EE + e);
        if (d >= 0 && d < NN && s >= 0 && s < NN) {
            int p = atomicAdd(&g_cursor[d], 1);
            if (p >= 0 && p < EE) g_csrc[p] = s;
        }
    }
}

// ---------------- fp32 -> bf16 hi/lo streaming split ----------------
__global__ void k_convA(const float* __restrict__ src, __nv_bfloat16* __restrict__ dh,
                        __nv_bfloat16* __restrict__ dl, int n4) {
    int i = blockIdx.x * blockDim.x + threadIdx.x;
    if (i >= n4) return;
    float4 v = *reinterpret_cast<const float4*>(src + (size_t)i * 4);
    __nv_bfloat16 h0 = __float2bfloat16(v.x), h1 = __float2bfloat16(v.y);
    __nv_bfloat16 h2 = __float2bfloat16(v.z), h3 = __float2bfloat16(v.w);
    __nv_bfloat162 ph0; ph0.x = h0; ph0.y = h1;
    __nv_bfloat162 ph1; ph1.x = h2; ph1.y = h3;
    __nv_bfloat162 pl0, pl1;
    pl0.x = __float2bfloat16(v.x - __bfloat162float(h0));
    pl0.y = __float2bfloat16(v.y - __bfloat162float(h1));
    pl1.x = __float2bfloat16(v.z - __bfloat162float(h2));
    pl1.y = __float2bfloat16(v.w - __bfloat162float(h3));
    *reinterpret_cast<__nv_bfloat162*>(dh + (size_t)i * 4) = ph0;
    *reinterpret_cast<__nv_bfloat162*>(dh + (size_t)i * 4 + 2) = ph1;
    *reinterpret_cast<__nv_bfloat162*>(dl + (size_t)i * 4) = pl0;
    *reinterpret_cast<__nv_bfloat162*>(dl + (size_t)i * 4 + 2) = pl1;
}

// weight [K][128] row-major -> transposed [128][K] hi/lo
__global__ void k_convW(const float* __restrict__ W, __nv_bfloat16* __restrict__ dh,
                        __nv_bfloat16* __restrict__ dl, int K) {
    int n = blockIdx.x;  // 0..127
    for (int k = threadIdx.x; k < K; k += blockDim.x) {
        float v = W[(size_t)k * HD + n];
        __nv_bfloat16 h = __float2bfloat16(v);
        dh[(size_t)n * K + k] = h;
        dl[(size_t)n * K + k] = __float2bfloat16(v - __bfloat162float(h));
    }
}

// ---------------- split-bf16 tensor-core GEMM (pre-converted operands) ----------------
__device__ __forceinline__ void mma16816(float* c, const uint32_t* a, uint32_t b0, uint32_t b1) {
    asm volatile(
        "mma.sync.aligned.m16n8k16.row.col.f32.bf16.bf16.f32 "
        "{%0,%1,%2,%3}, {%4,%5,%6,%7}, {%8,%9}, {%0,%1,%2,%3};"
        : "+f"(c[0]), "+f"(c[1]), "+f"(c[2]), "+f"(c[3])
        : "r"(a[0]), "r"(a[1]), "r"(a[2]), "r"(a[3]), "r"(b0), "r"(b1));
}

template <int K, bool LEAKY, bool ADDM, bool STATS, bool OUTBF>
__global__ void __launch_bounds__(256, 2) k_gemm_tc(
        const __nv_bfloat16* __restrict__ Ahg, const __nv_bfloat16* __restrict__ Alg,
        const __nv_bfloat16* __restrict__ Bhg, const __nv_bfloat16* __restrict__ Blg,  // [128][K]
        float* __restrict__ C, __nv_bfloat16* __restrict__ Ch, __nv_bfloat16* __restrict__ Cl,
        const float* __restrict__ bias, const float* __restrict__ addm,
        float* __restrict__ bnsum, float* __restrict__ bnsq) {
    __shared__ __nv_bfloat16 Ah[128 * AK], Al[128 * AK];
    __shared__ __nv_bfloat16 Bh[128 * AK], Bl[128 * AK];
    __shared__ float s_sum[128], s_sq[128];
    const int tid = threadIdx.x;
    const int m0 = blockIdx.x * 128;
    if (STATS && tid < 128) { s_sum[tid] = 0.f; s_sq[tid] = 0.f; }
    const int lane = tid & 31;
    const int wid = tid >> 5;
    const int g = lane >> 2, r = lane & 3;
    const int wm = (wid & 3) * 32;
    const int wn = (wid >> 2) * 64;

    float acc[2][8][4];
#pragma unroll
    for (int i = 0; i < 2; i++)
#pragma unroll
        for (int j = 0; j < 8; j++)
#pragma unroll
            for (int q = 0; q < 4; q++) acc[i][j][q] = 0.f;

    const int row = tid >> 1;          // 0..127 (shared by A and B tiles)
    const int koff = (tid & 1) * 8;    // 0 or 8
    const bool arow_ok = (m0 + row) < NN;
    const size_t abase = (size_t)(m0 + row) * K;
    const size_t bbase = (size_t)row * K;

    uint4 rah, ral, rbh, rbl;
    const uint4 z4 = make_uint4(0, 0, 0, 0);

    // stage chunk 0
    {
        int k0 = 0;
        rah = arow_ok ? *reinterpret_cast<const uint4*>(Ahg + abase + k0 + koff) : z4;
        ral = arow_ok ? *reinterpret_cast<const uint4*>(Alg + abase + k0 + koff) : z4;
        rbh = *reinterpret_cast<const uint4*>(Bhg + bbase + k0 + koff);
        rbl = *reinterpret_cast<const uint4*>(Blg + bbase + k0 + koff);
    }

    constexpr int NC = K / 16;
#pragma unroll
    for (int c = 0; c < NC; c++) {
        __syncthreads();   // WAR: previous compute done before overwrite
        *reinterpret_cast<uint4*>(&Ah[row * AK + koff]) = rah;
        *reinterpret_cast<uint4*>(&Al[row * AK + koff]) = ral;
        *reinterpret_cast<uint4*>(&Bh[row * AK + koff]) = rbh;
        *reinterpret_cast<uint4*>(&Bl[row * AK + koff]) = rbl;
        __syncthreads();
        if (c + 1 < NC) {   // stage next chunk (overlaps with MMA below)
            int k0 = (c + 1) * 16;
            rah = arow_ok ? *reinterpret_cast<const uint4*>(Ahg + abase + k0 + koff) : z4;
            ral = arow_ok ? *reinterpret_cast<const uint4*>(Alg + abase + k0 + koff) : z4;
            rbh = *reinterpret_cast<const uint4*>(Bhg + bbase + k0 + koff);
            rbl = *reinterpret_cast<const uint4*>(Blg + bbase + k0 + koff);
        }
        // fragments + MMA (layout identical to proven R8 code)
        uint32_t ah[2][4], al[2][4];
#pragma unroll
        for (int mi = 0; mi < 2; mi++) {
            int mr = wm + mi * 16;
            ah[mi][0] = *(const uint32_t*)&Ah[(mr + g) * AK + 2 * r];
            ah[mi][1] = *(const uint32_t*)&Ah[(mr + g + 8) * AK + 2 * r];
            ah[mi][2] = *(const uint32_t*)&Ah[(mr + g) * AK + 2 * r + 8];
            ah[mi][3] = *(const uint32_t*)&Ah[(mr + g + 8) * AK + 2 * r + 8];
            al[mi][0] = *(const uint32_t*)&Al[(mr + g) * AK + 2 * r];
            al[mi][1] = *(const uint32_t*)&Al[(mr + g + 8) * AK + 2 * r];
            al[mi][2] = *(const uint32_t*)&Al[(mr + g) * AK + 2 * r + 8];
            al[mi][3] = *(const uint32_t*)&Al[(mr + g + 8) * AK + 2 * r + 8];
        }
#pragma unroll
        for (int ni = 0; ni < 8; ni++) {
            int nr = (wn + ni * 8 + g) * AK;
            uint32_t bh0 = *(const uint32_t*)&Bh[nr + 2 * r];
            uint32_t bh1 = *(const uint32_t*)&Bh[nr + 2 * r + 8];
            uint32_t bl0 = *(const uint32_t*)&Bl[nr + 2 * r];
            uint32_t bl1 = *(const uint32_t*)&Bl[nr + 2 * r + 8];
#pragma unroll
            for (int mi = 0; mi < 2; mi++) {
                mma16816(acc[mi][ni], al[mi], bh0, bh1);
                mma16816(acc[mi][ni], ah[mi], bl0, bl1);
                mma16816(acc[mi][ni], ah[mi], bh0, bh1);
            }
        }
    }

    // ---- epilogue ----
#pragma unroll
    for (int mi = 0; mi < 2; mi++) {
#pragma unroll
        for (int ni = 0; ni < 8; ni++) {
            int mA = m0 + wm + mi * 16 + g;
            int mB = mA + 8;
            int n = wn + ni * 8 + 2 * r;
            float bc0 = bias ? bias[n] : 0.f;
            float bc1 = bias ? bias[n + 1] : 0.f;
            float v0 = acc[mi][ni][0] + bc0, v1 = acc[mi][ni][1] + bc1;
            float v2 = acc[mi][ni][2] + bc0, v3 = acc[mi][ni][3] + bc1;
            bool okA = mA < NN, okB = mB < NN;
            if (okA) {
                if (ADDM) { v0 += addm[(size_t)mA * HD + n]; v1 += addm[(size_t)mA * HD + n + 1]; }
                if (LEAKY) { v0 = lrelu(v0); v1 = lrelu(v1); }
                if (OUTBF) {
                    __nv_bfloat16 h0 = __float2bfloat16(v0), h1 = __float2bfloat16(v1);
                    __nv_bfloat162 ph; ph.x = h0; ph.y = h1;
                    __nv_bfloat162 pl;
                    pl.x = __float2bfloat16(v0 - __bfloat162float(h0));
                    pl.y = __float2bfloat16(v1 - __bfloat162float(h1));
                    *reinterpret_cast<__nv_bfloat162*>(Ch + (size_t)mA * HD + n) = ph;
                    *reinterpret_cast<__nv_bfloat162*>(Cl + (size_t)mA * HD + n) = pl;
                } else {
                    *(float2*)&C[(size_t)mA * HD + n] = make_float2(v0, v1);
                }
            }
            if (okB) {
                if (ADDM) { v2 += addm[(size_t)mB * HD + n]; v3 += addm[(size_t)mB * HD + n + 1]; }
                if (LEAKY) { v2 = lrelu(v2); v3 = lrelu(v3); }
                if (OUTBF) {
                    __nv_bfloat16 h2 = __float2bfloat16(v2), h3 = __float2bfloat16(v3);
                    __nv_bfloat162 ph; ph.x = h2; ph.y = h3;
                    __nv_bfloat162 pl;
                    pl.x = __float2bfloat16(v2 - __bfloat162float(h2));
                    pl.y = __float2bfloat16(v3 - __bfloat162float(h3));
                    *reinterpret_cast<__nv_bfloat162*>(Ch + (size_t)mB * HD + n) = ph;
                    *reinterpret_cast<__nv_bfloat162*>(Cl + (size_t)mB * HD + n) = pl;
                } else {
                    *(float2*)&C[(size_t)mB * HD + n] = make_float2(v2, v3);
                }
            }
            if (STATS && (okA || okB)) {
                float s0 = (okA ? v0 : 0.f) + (okB ? v2 : 0.f);
                float s1 = (okA ? v1 : 0.f) + (okB ? v3 : 0.f);
                float q0 = (okA ? v0 * v0 : 0.f) + (okB ? v2 * v2 : 0.f);
                float q1 = (okA ? v1 * v1 : 0.f) + (okB ? v3 * v3 : 0.f);
                atomicAdd(&s_sum[n], s0);
                atomicAdd(&s_sum[n + 1], s1);
                atomicAdd(&s_sq[n], q0);
                atomicAdd(&s_sq[n + 1], q1);
            }
        }
    }
    if (STATS) {
        __syncthreads();
        if (tid < 128) {
            atomicAdd(&bnsum[tid], s_sum[tid]);
            atomicAdd(&bnsq[tid], s_sq[tid]);
        }
    }
}

// ---------------- BN preps ----------------
__global__ void k_bnprep1(const float* __restrict__ gamma1, const float* __restrict__ beta1,
                          const float* __restrict__ W1) {
    int c = threadIdx.x;
    float mean = g_bnsum1[c] / (float)NN;
    float var = g_bnsq1[c] / (float)NN - mean * mean;
    float sc = gamma1[c] * rsqrtf(var + 1e-5f);
    float sh = beta1[c] - mean * sc;
    g_scale1[c] = sc;
    g_shift1[c] = sh;
    __syncthreads();
    float cj = 0.f;
    for (int k = 0; k < HD; k++) {
        cj += g_shift1[k] * W1[k * HD + c];
        g_W1p[k * HD + c] = g_scale1[k] * W1[k * HD + c];
    }
    g_c1[c] = cj;
}

__global__ void k_bnprep2(const float* __restrict__ gamma2, const float* __restrict__ beta2) {
    int c = threadIdx.x;
    float mean = g_bnsum2[c] / (float)NN;
    float var = g_bnsq2[c] / (float)NN - mean * mean;
    float sc = gamma2[c] * rsqrtf(var + 1e-5f);
    g_s2[c] = sc;
    g_sh2[c] = beta2[c] - mean * sc;
}

// ---------------- attention coefficients ----------------
__global__ void k_att1(const float* __restrict__ att_src, const float* __restrict__ att_dst) {
    int gt = blockIdx.x * blockDim.x + threadIdx.x;
    int w = gt >> 5, lane = gt & 31;
    if (w >= NN) return;
    float4 t4 = *reinterpret_cast<const float4*>(g_t1 + (size_t)w * HD + lane * 4);
    float4 s4 = *reinterpret_cast<const float4*>(att_src + lane * 4);
    float4 d4 = *reinterpret_cast<const float4*>(att_dst + lane * 4);
    float ps = t4.x * s4.x + t4.y * s4.y + t4.z * s4.z + t4.w * s4.w;
    float pd = t4.x * d4.x + t4.y * d4.y + t4.z * d4.z + t4.w * d4.w;
    ps += __shfl_xor_sync(0xFFFFFFFFu, ps, 1); ps += __shfl_xor_sync(0xFFFFFFFFu, ps, 2);
    pd += __shfl_xor_sync(0xFFFFFFFFu, pd, 1); pd += __shfl_xor_sync(0xFFFFFFFFu, pd, 2);
    if ((lane & 3) == 0) {
        g_as1[w * NHEADS + (lane >> 2)] = ps;
        g_ad1[w * NHEADS + (lane >> 2)] = pd;
    }
}

__global__ void k_att2(const float* __restrict__ att_src, const float* __restrict__ att_dst) {
    int gt = blockIdx.x * blockDim.x + threadIdx.x;
    int w = gt >> 5, lane = gt & 31;
    if (w >= NN) return;
    float4 t4 = *reinterpret_cast<const float4*>(g_t2 + (size_t)w * HD + lane * 4);
    float4 s4 = *reinterpret_cast<const float4*>(att_src + lane * 4);
    float4 d4 = *reinterpret_cast<const float4*>(att_dst + lane * 4);
    float ps = t4.x * s4.x + t4.y * s4.y + t4.z * s4.z + t4.w * s4.w;
    float pd = t4.x * d4.x + t4.y * d4.y + t4.z * d4.z + t4.w * d4.w;
#pragma unroll
    for (int off = 16; off; off >>= 1) {
        ps += __shfl_xor_sync(0xFFFFFFFFu, ps, off);
        pd += __shfl_xor_sync(0xFFFFFFFFu, pd, off);
    }
    if (lane == 0) { g_as2[w] = ps; g_ad2[w] = pd; }
}

// ---------------- softmax per dst ----------------
__global__ void k_softmax1() {
    int gt = blockIdx.x * blockDim.x + threadIdx.x;
    int w = gt >> 5, lane = gt & 31;
    if (w >= NN) return;
    int beg = g_rowptr[w], end = g_rowptr[w + 1];
    if (beg == end) return;
    int h = lane & 7, es = lane >> 3;
    float ad = g_ad1[w * NHEADS + h];
    float mx = -INFINITY;
    for (int j = beg + es; j < end; j += 4) {
        int s = g_csrc[j];
        float v = lrelu(g_as1[s * NHEADS + h] + ad);
        mx = fmaxf(mx, v);
    }
    mx = fmaxf(mx, __shfl_xor_sync(0xFFFFFFFFu, mx, 8));
    mx = fmaxf(mx, __shfl_xor_sync(0xFFFFFFFFu, mx, 16));
    float den = 0.f;
    for (int j = beg + es; j < end; j += 4) {
        int s = g_csrc[j];
        float v = lrelu(g_as1[s * NHEADS + h] + ad);
        den += __expf(v - mx);
    }
    den += __shfl_xor_sync(0xFFFFFFFFu, den, 8);
    den += __shfl_xor_sync(0xFFFFFFFFu, den, 16);
    float inv = 1.f / fmaxf(den, 1e-16f);
    for (int j = beg + es; j < end; j += 4) {
        int s = g_csrc[j];
        float v = lrelu(g_as1[s * NHEADS + h] + ad);
        g_alpha1[(size_t)j * NHEADS + h] = __expf(v - mx) * inv;
    }
}

__global__ void k_softmax2() {
    int gt = blockIdx.x * blockDim.x + threadIdx.x;
    int w = gt >> 5, lane = gt & 31;
    if (w >= NN) return;
    int beg = g_rowptr[w], end = g_rowptr[w + 1];
    if (beg == end) return;
    float ad = g_ad2[w];
    float mx = -INFINITY;
    for (int j = beg + lane; j < end; j += 32) {
        float v = lrelu(g_as2[g_csrc[j]] + ad);
        mx = fmaxf(mx, v);
    }
#pragma unroll
    for (int off = 16; off; off >>= 1) mx = fmaxf(mx, __shfl_xor_sync(0xFFFFFFFFu, mx, off));
    float den = 0.f;
    for (int j = beg + lane; j < end; j += 32) {
        float v = lrelu(g_as2[g_csrc[j]] + ad);
        den += __expf(v - mx);
    }
#pragma unroll
    for (int off = 16; off; off >>= 1) den += __shfl_xor_sync(0xFFFFFFFFu, den, off);
    float inv = 1.f / fmaxf(den, 1e-16f);
    for (int j = beg + lane; j < end; j += 32) {
        float v = lrelu(g_as2[g_csrc[j]] + ad);
        g_alpha2[j] = __expf(v - mx) * inv;
    }
}

// ---------------- aggregation ----------------
__global__ void k_agg1(const float* __restrict__ bias1) {
    int gt = blockIdx.x * blockDim.x + threadIdx.x;
    int w = gt >> 5, lane = gt & 31;
    if (w >= NN) return;
    int beg = g_rowptr[w], end = g_rowptr[w + 1];
    int hh = lane >> 2;
    float ax = 0.f, ay = 0.f, az = 0.f, aw = 0.f;
#pragma unroll 2
    for (int j = beg; j < end; j++) {
        int s = g_csrc[j];
        float a = g_alpha1[(size_t)j * NHEADS + hh];
        float4 t4 = *reinterpret_cast<const float4*>(g_t1 + (size_t)s * HD + lane * 4);
        ax += a * t4.x; ay += a * t4.y; az += a * t4.z; aw += a * t4.w;
    }
    float4 b4 = *reinterpret_cast<const float4*>(bias1 + lane * 4);
    float v0 = lrelu(ax + b4.x), v1 = lrelu(ay + b4.y);
    float v2 = lrelu(az + b4.z), v3 = lrelu(aw + b4.w);
    // out1 only feeds GEMM A operands -> store hi/lo bf16 directly
    size_t base = (size_t)w * HD + lane * 4;
    __nv_bfloat16 h0 = __float2bfloat16(v0), h1 = __float2bfloat16(v1);
    __nv_bfloat16 h2 = __float2bfloat16(v2), h3 = __float2bfloat16(v3);
    __nv_bfloat162 ph0; ph0.x = h0; ph0.y = h1;
    __nv_bfloat162 ph1; ph1.x = h2; ph1.y = h3;
    __nv_bfloat162 pl0, pl1;
    pl0.x = __float2bfloat16(v0 - __bfloat162float(h0));
    pl0.y = __float2bfloat16(v1 - __bfloat162float(h1));
    pl1.x = __float2bfloat16(v2 - __bfloat162float(h2));
    pl1.y = __float2bfloat16(v3 - __bfloat162float(h3));
    *reinterpret_cast<__nv_bfloat162*>(g_o1h + base) = ph0;
    *reinterpret_cast<__nv_bfloat162*>(g_o1h + base + 2) = ph1;
    *reinterpret_cast<__nv_bfloat162*>(g_o1l + base) = pl0;
    *reinterpret_cast<__nv_bfloat162*>(g_o1l + base + 2) = pl1;
}

__global__ void k_agg2(const float* __restrict__ bias2) {
    int gt = blockIdx.x * blockDim.x + threadIdx.x;
    int w = gt >> 5, lane = gt & 31;
    if (w >= NN) return;
    int beg = g_rowptr[w], end = g_rowptr[w + 1];
    float ax = 0.f, ay = 0.f, az = 0.f, aw = 0.f;
#pragma unroll 2
    for (int j = beg; j < end; j++) {
        int s = g_csrc[j];
        float a = g_alpha2[j];
        float4 t4 = *reinterpret_cast<const float4*>(g_t2 + (size_t)s * HD + lane * 4);
        ax += a * t4.x; ay += a * t4.y; az += a * t4.z; aw += a * t4.w;
    }
    float4 b4 = *reinterpret_cast<const float4*>(bias2 + lane * 4);
    float4 o = make_float4(ax + b4.x, ay + b4.y, az + b4.z, aw + b4.w);
    *reinterpret_cast<float4*>(g_conv2 + (size_t)w * HD + lane * 4) = o;
}

// ---------------- final: BN2 apply + row L2 normalize ----------------
__global__ void k_final(float* __restrict__ out) {
    int gt = blockIdx.x * blockDim.x + threadIdx.x;
    int w = gt >> 5, lane = gt & 31;
    if (w >= NN) return;
    float4 h4 = *reinterpret_cast<const float4*>(g_h2 + (size_t)w * HD + lane * 4);
    float4 s4 = *reinterpret_cast<const float4*>(g_s2 + lane * 4);
    float4 sh4 = *reinterpret_cast<const float4*>(g_sh2 + lane * 4);
    float4 y;
    y.x = h4.x * s4.x + sh4.x; y.y = h4.y * s4.y + sh4.y;
    y.z = h4.z * s4.z + sh4.z; y.w = h4.w * s4.w + sh4.w;
    float ss = y.x * y.x + y.y * y.y + y.z * y.z + y.w * y.w;
#pragma unroll
    for (int off = 16; off; off >>= 1) ss += __shfl_xor_sync(0xFFFFFFFFu, ss, off);
    float inv = 1.f / fmaxf(sqrtf(ss), 1e-12f);
    y.x *= inv; y.y *= inv; y.z *= inv; y.w *= inv;
    *reinterpret_cast<float4*>(out + (size_t)w * HD + lane * 4) = y;
}

// ---------------- host launcher ----------------
extern "C" void kernel_launch(void* const* d_in, const int* in_sizes, int n_in,
                              void* d_out, int out_size) {
    const float* x        = (const float*)d_in[0];
    const float* W_in     = (const float*)d_in[1];
    const float* b_in     = (const float*)d_in[2];
    const float* gamma1   = (const float*)d_in[3];
    const float* beta1    = (const float*)d_in[4];
    const float* W1       = (const float*)d_in[5];
    const float* att_src1 = (const float*)d_in[6];
    const float* att_dst1 = (const float*)d_in[7];
    const float* bias1    = (const float*)d_in[8];
    const float* W2       = (const float*)d_in[9];
    const float* att_src2 = (const float*)d_in[10];
    const float* att_dst2 = (const float*)d_in[11];
    const float* bias2    = (const float*)d_in[12];
    const float* W_skip   = (const float*)d_in[13];
    const float* b_skip   = (const float*)d_in[14];
    const float* gamma2   = (const float*)d_in[15];
    const float* beta2    = (const float*)d_in[16];
    const void*  ei       = (const void*)d_in[17];
    float* out = (float*)d_out;

    __nv_bfloat16 *p_xh, *p_xl, *p_h0h, *p_h0l, *p_o1h, *p_o1l;
    __nv_bfloat16 *p_Winth, *p_Wintl, *p_W1th, *p_W1tl, *p_W2th, *p_W2tl, *p_Wsth, *p_Wstl;
    float *p_t1, *p_t2, *p_conv2, *p_h2, *p_W1p, *p_c1;
    float *p_bnsum1, *p_bnsq1, *p_bnsum2, *p_bnsq2;
    cudaGetSymbolAddress((void**)&p_xh, g_xh);
    cudaGetSymbolAddress((void**)&p_xl, g_xl);
    cudaGetSymbolAddress((void**)&p_h0h, g_h0h);
    cudaGetSymbolAddress((void**)&p_h0l, g_h0l);
    cudaGetSymbolAddress((void**)&p_o1h, g_o1h);
    cudaGetSymbolAddress((void**)&p_o1l, g_o1l);
    cudaGetSymbolAddress((void**)&p_Winth, g_Winth);
    cudaGetSymbolAddress((void**)&p_Wintl, g_Wintl);
    cudaGetSymbolAddress((void**)&p_W1th, g_W1th);
    cudaGetSymbolAddress((void**)&p_W1tl, g_W1tl);
    cudaGetSymbolAddress((void**)&p_W2th, g_W2th);
    cudaGetSymbolAddress((void**)&p_W2tl, g_W2tl);
    cudaGetSymbolAddress((void**)&p_Wsth, g_Wsth);
    cudaGetSymbolAddress((void**)&p_Wstl, g_Wstl);
    cudaGetSymbolAddress((void**)&p_t1, g_t1);
    cudaGetSymbolAddress((void**)&p_t2, g_t2);
    cudaGetSymbolAddress((void**)&p_conv2, g_conv2);
    cudaGetSymbolAddress((void**)&p_h2, g_h2);
    cudaGetSymbolAddress((void**)&p_W1p, g_W1p);
    cudaGetSymbolAddress((void**)&p_c1, g_c1);
    cudaGetSymbolAddress((void**)&p_bnsum1, g_bnsum1);
    cudaGetSymbolAddress((void**)&p_bnsq1, g_bnsq1);
    cudaGetSymbolAddress((void**)&p_bnsum2, g_bnsum2);
    cudaGetSymbolAddress((void**)&p_bnsq2, g_bnsq2);

    const int nb_edge = (EE + 255) / 256;
    const int nb_node = (NN * 32 + 255) / 256;
    const int gemm_grid = (NN + 127) / 128;

    k_detect<<<1, 1>>>(ei);
    k_zero<<<(NN + 255) / 256, 256>>>();
    k_count<<<nb_edge, 256>>>(ei);
    k_scanA<<<NSCAN, SCAN_BLK>>>();
    k_scanB<<<1, SCAN_BLK>>>();
    k_scanC<<<NSCAN, SCAN_BLK>>>();
    k_fill<<<nb_edge, 256>>>(ei);

    // operand conversions
    k_convA<<<(NN * IND / 4 + 255) / 256, 256>>>(x, p_xh, p_xl, NN * IND / 4);
    k_convW<<<HD, 256>>>(W_in, p_Winth, p_Wintl, IND);
    k_convW<<<HD, 256>>>(W2, p_W2th, p_W2tl, HD);
    k_convW<<<HD, 256>>>(W_skip, p_Wsth, p_Wstl, HD);

    // GEMM1: h0 = leaky(x @ W_in + b_in) -> bf16 pair, BN1 stats
    k_gemm_tc<IND, true, false, true, true><<<gemm_grid, 256>>>(
        p_xh, p_xl, p_Winth, p_Wintl, nullptr, p_h0h, p_h0l, b_in, nullptr, p_bnsum1, p_bnsq1);
    k_bnprep1<<<1, HD>>>(gamma1, beta1, W1);
    k_convW<<<HD, 256>>>(p_W1p, p_W1th, p_W1tl, HD);
    // GEMM2: t1 = h0 @ W1p + c1 (BN folded)
    k_gemm_tc<HD, false, false, false, false><<<gemm_grid, 256>>>(
        p_h0h, p_h0l, p_W1th, p_W1tl, p_t1, nullptr, nullptr, p_c1, nullptr, nullptr, nullptr);
    k_att1<<<nb_node, 256>>>(att_src1, att_dst1);
    k_softmax1<<<nb_node, 256>>>();
    k_agg1<<<nb_node, 256>>>(bias1);
    // GEMM3: t2 = out1 @ W2
    k_gemm_tc<HD, false, false, false, false><<<gemm_grid, 256>>>(
        p_o1h, p_o1l, p_W2th, p_W2tl, p_t2, nullptr, nullptr, nullptr, nullptr, nullptr, nullptr);
    k_att2<<<nb_node, 256>>>(att_src2, att_dst2);
    k_softmax2<<<nb_node, 256>>>();
    k_agg2<<<nb_node, 256>>>(bias2);
    // GEMM4: h2 = conv2 + out1 @ W_skip + b_skip, BN2 stats
    k_gemm_tc<HD, false, true, true, false><<<gemm_grid, 256>>>(
        p_o1h, p_o1l, p_Wsth, p_Wstl, p_h2, nullptr, nullptr, b_skip, p_conv2, p_bnsum2, p_bnsq2);
    k_bnprep2<<<1, HD>>>(gamma2, beta2);
    k_final<<<nb_node, 256>>>(out);
}

// round 10
// speedup vs baseline: 1.3288x; 1.0301x over previous
#include <cuda_runtime.h>
#include <cuda_bf16.h>
#include <stdint.h>
#include <math.h>

// ---------------- problem constants ----------------
#define NN 50000
#define EE 800000
#define IND 256
#define HD 128
#define NHEADS 8
#define SCAN_BLK 256
#define NSCAN ((NN + SCAN_BLK - 1) / SCAN_BLK)
#define AK 24   // smem bf16 row stride (48B)

// ---------------- scratch ----------------
__device__ __align__(16) __nv_bfloat16 g_xh[(size_t)NN * IND], g_xl[(size_t)NN * IND];
__device__ __align__(16) __nv_bfloat16 g_h0h[NN * HD], g_h0l[NN * HD];
__device__ __align__(16) __nv_bfloat16 g_o1h[NN * HD], g_o1l[NN * HD];
__device__ __align__(16) __nv_bfloat16 g_Winth[HD * IND], g_Wintl[HD * IND];
__device__ __align__(16) __nv_bfloat16 g_W1th[HD * HD], g_W1tl[HD * HD];
__device__ __align__(16) __nv_bfloat16 g_W2th[HD * HD], g_W2tl[HD * HD];
__device__ __align__(16) __nv_bfloat16 g_Wsth[HD * HD], g_Wstl[HD * HD];
__device__ __align__(16) float g_t1[NN * HD];
__device__ __align__(16) float g_t2[NN * HD];
__device__ __align__(16) float g_conv2[NN * HD];
__device__ __align__(16) float g_h2[NN * HD];
__device__ __align__(16) float g_as1[NN * NHEADS], g_ad1[NN * NHEADS];
__device__ __align__(16) float g_as2[NN], g_ad2[NN];
__device__ __align__(16) int   g_cnt[NN];
__device__ __align__(16) int   g_scantmp[NN];
__device__ __align__(16) int   g_blksum[SCAN_BLK];
__device__ __align__(16) int   g_blkoff[SCAN_BLK];
__device__ int   g_total;
__device__ __align__(16) int   g_rowptr[NN + 1];
__device__ __align__(16) int   g_cursor[NN];
__device__ __align__(16) int   g_csrc[EE];
__device__ __align__(16) float g_bnsum1[HD], g_bnsq1[HD], g_bnsum2[HD], g_bnsq2[HD];
__device__ __align__(16) float g_scale1[HD], g_shift1[HD];
__device__ __align__(16) float g_W1p[HD * HD], g_c1[HD];
__device__ __align__(16) float g_s2[HD], g_sh2[HD];
__device__ int g_is64;

__device__ __forceinline__ float lrelu(float v) { return v >= 0.f ? v : 0.2f * v; }

__device__ __forceinline__ int edge_idx(const void* ei, long long pos) {
    if (g_is64) return (int)((const long long*)ei)[pos];
    return ((const int*)ei)[pos];
}

// ---------------- dtype detection ----------------
__global__ void k_detect(const void* ei) {
    const long long* q = (const long long*)ei;
    int ok = 1;
    for (int i = 0; i < 64; i++) {
        long long v = q[i];
        if (v < 0 || v >= NN) { ok = 0; break; }
    }
    g_is64 = ok;
}

// ---------------- zero ----------------
__global__ void k_zero() {
    int i = blockIdx.x * blockDim.x + threadIdx.x;
    if (i < NN) g_cnt[i] = 0;
    if (i < HD) { g_bnsum1[i] = 0.f; g_bnsq1[i] = 0.f; g_bnsum2[i] = 0.f; g_bnsq2[i] = 0.f; }
}

// ---------------- CSR build ----------------
__global__ void k_count(const void* __restrict__ ei) {
    int e = blockIdx.x * blockDim.x + threadIdx.x;
    if (e < EE) {
        int d = edge_idx(ei, (long long)EE + e);
        if (d >= 0 && d < NN) atomicAdd(&g_cnt[d], 1);
    }
}

__global__ void k_scanA() {
    __shared__ int sh[SCAN_BLK];
    int tid = threadIdx.x;
    int i = blockIdx.x * SCAN_BLK + tid;
    int v = (i < NN) ? g_cnt[i] : 0;
    sh[tid] = v;
    __syncthreads();
#pragma unroll
    for (int off = 1; off < SCAN_BLK; off <<= 1) {
        int t = (tid >= off) ? sh[tid - off] : 0;
        __syncthreads();
        sh[tid] += t;
        __syncthreads();
    }
    if (i < NN) g_scantmp[i] = sh[tid];
    if (tid == SCAN_BLK - 1) g_blksum[blockIdx.x] = sh[tid];
}

__global__ void k_scanB() {
    __shared__ int sh[SCAN_BLK];
    int tid = threadIdx.x;
    int v = (tid < NSCAN) ? g_blksum[tid] : 0;
    sh[tid] = v;
    __syncthreads();
#pragma unroll
    for (int off = 1; off < SCAN_BLK; off <<= 1) {
        int t = (tid >= off) ? sh[tid - off] : 0;
        __syncthreads();
        sh[tid] += t;
        __syncthreads();
    }
    g_blkoff[tid] = sh[tid] - v;
    if (tid == SCAN_BLK - 1) g_total = sh[tid];
}

__global__ void k_scanC() {
    int i = blockIdx.x * blockDim.x + threadIdx.x;
    if (i < NN) {
        int r = g_blkoff[blockIdx.x] + g_scantmp[i] - g_cnt[i];
        g_rowptr[i] = r;
        g_cursor[i] = r;
    }
    if (i == 0) g_rowptr[NN] = g_total;
}

__global__ void k_fill(const void* __restrict__ ei) {
    int e = blockIdx.x * blockDim.x + threadIdx.x;
    if (e < EE) {
        int s = edge_idx(ei, e);
        int d = edge_idx(ei, (long long)EE + e);
        if (d >= 0 && d < NN && s >= 0 && s < NN) {
            int p = atomicAdd(&g_cursor[d], 1);
            if (p >= 0 && p < EE) g_csrc[p] = s;
        }
    }
}

// ---------------- fp32 -> bf16 hi/lo streaming split ----------------
__global__ void k_convA(const float* __restrict__ src, __nv_bfloat16* __restrict__ dh,
                        __nv_bfloat16* __restrict__ dl, int n4) {
    int i = blockIdx.x * blockDim.x + threadIdx.x;
    if (i >= n4) return;
    float4 v = *reinterpret_cast<const float4*>(src + (size_t)i * 4);
    __nv_bfloat16 h0 = __float2bfloat16(v.x), h1 = __float2bfloat16(v.y);
    __nv_bfloat16 h2 = __float2bfloat16(v.z), h3 = __float2bfloat16(v.w);
    __nv_bfloat162 ph0; ph0.x = h0; ph0.y = h1;
    __nv_bfloat162 ph1; ph1.x = h2; ph1.y = h3;
    __nv_bfloat162 pl0, pl1;
    pl0.x = __float2bfloat16(v.x - __bfloat162float(h0));
    pl0.y = __float2bfloat16(v.y - __bfloat162float(h1));
    pl1.x = __float2bfloat16(v.z - __bfloat162float(h2));
    pl1.y = __float2bfloat16(v.w - __bfloat162float(h3));
    *reinterpret_cast<__nv_bfloat162*>(dh + (size_t)i * 4) = ph0;
    *reinterpret_cast<__nv_bfloat162*>(dh + (size_t)i * 4 + 2) = ph1;
    *reinterpret_cast<__nv_bfloat162*>(dl + (size_t)i * 4) = pl0;
    *reinterpret_cast<__nv_bfloat162*>(dl + (size_t)i * 4 + 2) = pl1;
}

__global__ void k_convW(const float* __restrict__ W, __nv_bfloat16* __restrict__ dh,
                        __nv_bfloat16* __restrict__ dl, int K) {
    int n = blockIdx.x;
    for (int k = threadIdx.x; k < K; k += blockDim.x) {
        float v = W[(size_t)k * HD + n];
        __nv_bfloat16 h = __float2bfloat16(v);
        dh[(size_t)n * K + k] = h;
        dl[(size_t)n * K + k] = __float2bfloat16(v - __bfloat162float(h));
    }
}

// ---------------- split-bf16 tensor-core GEMM ----------------
__device__ __forceinline__ void mma16816(float* c, const uint32_t* a, uint32_t b0, uint32_t b1) {
    asm volatile(
        "mma.sync.aligned.m16n8k16.row.col.f32.bf16.bf16.f32 "
        "{%0,%1,%2,%3}, {%4,%5,%6,%7}, {%8,%9}, {%0,%1,%2,%3};"
        : "+f"(c[0]), "+f"(c[1]), "+f"(c[2]), "+f"(c[3])
        : "r"(a[0]), "r"(a[1]), "r"(a[2]), "r"(a[3]), "r"(b0), "r"(b1));
}

template <int K, bool LEAKY, bool ADDM, bool STATS, bool OUTBF>
__global__ void __launch_bounds__(256, 2) k_gemm_tc(
        const __nv_bfloat16* __restrict__ Ahg, const __nv_bfloat16* __restrict__ Alg,
        const __nv_bfloat16* __restrict__ Bhg, const __nv_bfloat16* __restrict__ Blg,
        float* __restrict__ C, __nv_bfloat16* __restrict__ Ch, __nv_bfloat16* __restrict__ Cl,
        const float* __restrict__ bias, const float* __restrict__ addm,
        float* __restrict__ bnsum, float* __restrict__ bnsq) {
    __shared__ __nv_bfloat16 Ah[128 * AK], Al[128 * AK];
    __shared__ __nv_bfloat16 Bh[128 * AK], Bl[128 * AK];
    __shared__ float s_sum[128], s_sq[128];
    const int tid = threadIdx.x;
    const int m0 = blockIdx.x * 128;
    if (STATS && tid < 128) { s_sum[tid] = 0.f; s_sq[tid] = 0.f; }
    const int lane = tid & 31;
    const int wid = tid >> 5;
    const int g = lane >> 2, r = lane & 3;
    const int wm = (wid & 3) * 32;
    const int wn = (wid >> 2) * 64;

    float acc[2][8][4];
#pragma unroll
    for (int i = 0; i < 2; i++)
#pragma unroll
        for (int j = 0; j < 8; j++)
#pragma unroll
            for (int q = 0; q < 4; q++) acc[i][j][q] = 0.f;

    const int row = tid >> 1;
    const int koff = (tid & 1) * 8;
    const bool arow_ok = (m0 + row) < NN;
    const size_t abase = (size_t)(m0 + row) * K;
    const size_t bbase = (size_t)row * K;

    uint4 rah, ral, rbh, rbl;
    const uint4 z4 = make_uint4(0, 0, 0, 0);

    {
        rah = arow_ok ? *reinterpret_cast<const uint4*>(Ahg + abase + koff) : z4;
        ral = arow_ok ? *reinterpret_cast<const uint4*>(Alg + abase + koff) : z4;
        rbh = *reinterpret_cast<const uint4*>(Bhg + bbase + koff);
        rbl = *reinterpret_cast<const uint4*>(Blg + bbase + koff);
    }

    constexpr int NC = K / 16;
#pragma unroll
    for (int c = 0; c < NC; c++) {
        __syncthreads();
        *reinterpret_cast<uint4*>(&Ah[row * AK + koff]) = rah;
        *reinterpret_cast<uint4*>(&Al[row * AK + koff]) = ral;
        *reinterpret_cast<uint4*>(&Bh[row * AK + koff]) = rbh;
        *reinterpret_cast<uint4*>(&Bl[row * AK + koff]) = rbl;
        __syncthreads();
        if (c + 1 < NC) {
            int k0 = (c + 1) * 16;
            rah = arow_ok ? *reinterpret_cast<const uint4*>(Ahg + abase + k0 + koff) : z4;
            ral = arow_ok ? *reinterpret_cast<const uint4*>(Alg + abase + k0 + koff) : z4;
            rbh = *reinterpret_cast<const uint4*>(Bhg + bbase + k0 + koff);
            rbl = *reinterpret_cast<const uint4*>(Blg + bbase + k0 + koff);
        }
        uint32_t ah[2][4], al[2][4];
#pragma unroll
        for (int mi = 0; mi < 2; mi++) {
            int mr = wm + mi * 16;
            ah[mi][0] = *(const uint32_t*)&Ah[(mr + g) * AK + 2 * r];
            ah[mi][1] = *(const uint32_t*)&Ah[(mr + g + 8) * AK + 2 * r];
            ah[mi][2] = *(const uint32_t*)&Ah[(mr + g) * AK + 2 * r + 8];
            ah[mi][3] = *(const uint32_t*)&Ah[(mr + g + 8) * AK + 2 * r + 8];
            al[mi][0] = *(const uint32_t*)&Al[(mr + g) * AK + 2 * r];
            al[mi][1] = *(const uint32_t*)&Al[(mr + g + 8) * AK + 2 * r];
            al[mi][2] = *(const uint32_t*)&Al[(mr + g) * AK + 2 * r + 8];
            al[mi][3] = *(const uint32_t*)&Al[(mr + g + 8) * AK + 2 * r + 8];
        }
#pragma unroll
        for (int ni = 0; ni < 8; ni++) {
            int nr = (wn + ni * 8 + g) * AK;
            uint32_t bh0 = *(const uint32_t*)&Bh[nr + 2 * r];
            uint32_t bh1 = *(const uint32_t*)&Bh[nr + 2 * r + 8];
            uint32_t bl0 = *(const uint32_t*)&Bl[nr + 2 * r];
            uint32_t bl1 = *(const uint32_t*)&Bl[nr + 2 * r + 8];
#pragma unroll
            for (int mi = 0; mi < 2; mi++) {
                mma16816(acc[mi][ni], al[mi], bh0, bh1);
                mma16816(acc[mi][ni], ah[mi], bl0, bl1);
                mma16816(acc[mi][ni], ah[mi], bh0, bh1);
            }
        }
    }

#pragma unroll
    for (int mi = 0; mi < 2; mi++) {
#pragma unroll
        for (int ni = 0; ni < 8; ni++) {
            int mA = m0 + wm + mi * 16 + g;
            int mB = mA + 8;
            int n = wn + ni * 8 + 2 * r;
            float bc0 = bias ? bias[n] : 0.f;
            float bc1 = bias ? bias[n + 1] : 0.f;
            float v0 = acc[mi][ni][0] + bc0, v1 = acc[mi][ni][1] + bc1;
            float v2 = acc[mi][ni][2] + bc0, v3 = acc[mi][ni][3] + bc1;
            bool okA = mA < NN, okB = mB < NN;
            if (okA) {
                if (ADDM) { v0 += addm[(size_t)mA * HD + n]; v1 += addm[(size_t)mA * HD + n + 1]; }
                if (LEAKY) { v0 = lrelu(v0); v1 = lrelu(v1); }
                if (OUTBF) {
                    __nv_bfloat16 h0 = __float2bfloat16(v0), h1 = __float2bfloat16(v1);
                    __nv_bfloat162 ph; ph.x = h0; ph.y = h1;
                    __nv_bfloat162 pl;
                    pl.x = __float2bfloat16(v0 - __bfloat162float(h0));
                    pl.y = __float2bfloat16(v1 - __bfloat162float(h1));
                    *reinterpret_cast<__nv_bfloat162*>(Ch + (size_t)mA * HD + n) = ph;
                    *reinterpret_cast<__nv_bfloat162*>(Cl + (size_t)mA * HD + n) = pl;
                } else {
                    *(float2*)&C[(size_t)mA * HD + n] = make_float2(v0, v1);
                }
            }
            if (okB) {
                if (ADDM) { v2 += addm[(size_t)mB * HD + n]; v3 += addm[(size_t)mB * HD + n + 1]; }
                if (LEAKY) { v2 = lrelu(v2); v3 = lrelu(v3); }
                if (OUTBF) {
                    __nv_bfloat16 h2 = __float2bfloat16(v2), h3 = __float2bfloat16(v3);
                    __nv_bfloat162 ph; ph.x = h2; ph.y = h3;
                    __nv_bfloat162 pl;
                    pl.x = __float2bfloat16(v2 - __bfloat162float(h2));
                    pl.y = __float2bfloat16(v3 - __bfloat162float(h3));
                    *reinterpret_cast<__nv_bfloat162*>(Ch + (size_t)mB * HD + n) = ph;
                    *reinterpret_cast<__nv_bfloat162*>(Cl + (size_t)mB * HD + n) = pl;
                } else {
                    *(float2*)&C[(size_t)mB * HD + n] = make_float2(v2, v3);
                }
            }
            if (STATS && (okA || okB)) {
                float s0 = (okA ? v0 : 0.f) + (okB ? v2 : 0.f);
                float s1 = (okA ? v1 : 0.f) + (okB ? v3 : 0.f);
                float q0 = (okA ? v0 * v0 : 0.f) + (okB ? v2 * v2 : 0.f);
                float q1 = (okA ? v1 * v1 : 0.f) + (okB ? v3 * v3 : 0.f);
                atomicAdd(&s_sum[n], s0);
                atomicAdd(&s_sum[n + 1], s1);
                atomicAdd(&s_sq[n], q0);
                atomicAdd(&s_sq[n + 1], q1);
            }
        }
    }
    if (STATS) {
        __syncthreads();
        if (tid < 128) {
            atomicAdd(&bnsum[tid], s_sum[tid]);
            atomicAdd(&bnsq[tid], s_sq[tid]);
        }
    }
}

// ---------------- BN preps ----------------
__global__ void k_bnprep1(const float* __restrict__ gamma1, const float* __restrict__ beta1,
                          const float* __restrict__ W1) {
    int c = threadIdx.x;
    float mean = g_bnsum1[c] / (float)NN;
    float var = g_bnsq1[c] / (float)NN - mean * mean;
    float sc = gamma1[c] * rsqrtf(var + 1e-5f);
    float sh = beta1[c] - mean * sc;
    g_scale1[c] = sc;
    g_shift1[c] = sh;
    __syncthreads();
    float cj = 0.f;
    for (int k = 0; k < HD; k++) {
        cj += g_shift1[k] * W1[k * HD + c];
        g_W1p[k * HD + c] = g_scale1[k] * W1[k * HD + c];
    }
    g_c1[c] = cj;
}

__global__ void k_bnprep2(const float* __restrict__ gamma2, const float* __restrict__ beta2) {
    int c = threadIdx.x;
    float mean = g_bnsum2[c] / (float)NN;
    float var = g_bnsq2[c] / (float)NN - mean * mean;
    float sc = gamma2[c] * rsqrtf(var + 1e-5f);
    g_s2[c] = sc;
    g_sh2[c] = beta2[c] - mean * sc;
}

// ---------------- attention coefficients ----------------
__global__ void k_att1(const float* __restrict__ att_src, const float* __restrict__ att_dst) {
    int gt = blockIdx.x * blockDim.x + threadIdx.x;
    int w = gt >> 5, lane = gt & 31;
    if (w >= NN) return;
    float4 t4 = *reinterpret_cast<const float4*>(g_t1 + (size_t)w * HD + lane * 4);
    float4 s4 = *reinterpret_cast<const float4*>(att_src + lane * 4);
    float4 d4 = *reinterpret_cast<const float4*>(att_dst + lane * 4);
    float ps = t4.x * s4.x + t4.y * s4.y + t4.z * s4.z + t4.w * s4.w;
    float pd = t4.x * d4.x + t4.y * d4.y + t4.z * d4.z + t4.w * d4.w;
    ps += __shfl_xor_sync(0xFFFFFFFFu, ps, 1); ps += __shfl_xor_sync(0xFFFFFFFFu, ps, 2);
    pd += __shfl_xor_sync(0xFFFFFFFFu, pd, 1); pd += __shfl_xor_sync(0xFFFFFFFFu, pd, 2);
    if ((lane & 3) == 0) {
        g_as1[w * NHEADS + (lane >> 2)] = ps;
        g_ad1[w * NHEADS + (lane >> 2)] = pd;
    }
}

__global__ void k_att2(const float* __restrict__ att_src, const float* __restrict__ att_dst) {
    int gt = blockIdx.x * blockDim.x + threadIdx.x;
    int w = gt >> 5, lane = gt & 31;
    if (w >= NN) return;
    float4 t4 = *reinterpret_cast<const float4*>(g_t2 + (size_t)w * HD + lane * 4);
    float4 s4 = *reinterpret_cast<const float4*>(att_src + lane * 4);
    float4 d4 = *reinterpret_cast<const float4*>(att_dst + lane * 4);
    float ps = t4.x * s4.x + t4.y * s4.y + t4.z * s4.z + t4.w * s4.w;
    float pd = t4.x * d4.x + t4.y * d4.y + t4.z * d4.z + t4.w * d4.w;
#pragma unroll
    for (int off = 16; off; off >>= 1) {
        ps += __shfl_xor_sync(0xFFFFFFFFu, ps, off);
        pd += __shfl_xor_sync(0xFFFFFFFFu, pd, off);
    }
    if (lane == 0) { g_as2[w] = ps; g_ad2[w] = pd; }
}

// ---------------- fused softmax + aggregation, conv1 ----------------
__global__ void k_sagg1(const float* __restrict__ bias1) {
    int gt = blockIdx.x * blockDim.x + threadIdx.x;
    int w = gt >> 5, lane = gt & 31;
    if (w >= NN) return;
    int beg = g_rowptr[w], end = g_rowptr[w + 1];

    // softmax stats: h8 = head (lane&7), es = edge slot (lane>>3), 4 edges in parallel
    int h8 = lane & 7, es = lane >> 3;
    float ad8 = g_ad1[w * NHEADS + h8];
    float mx = -INFINITY;
    for (int j = beg + es; j < end; j += 4) {
        int s = g_csrc[j];
        mx = fmaxf(mx, lrelu(g_as1[s * NHEADS + h8] + ad8));
    }
    mx = fmaxf(mx, __shfl_xor_sync(0xFFFFFFFFu, mx, 8));
    mx = fmaxf(mx, __shfl_xor_sync(0xFFFFFFFFu, mx, 16));
    float den = 0.f;
    for (int j = beg + es; j < end; j += 4) {
        int s = g_csrc[j];
        den += __expf(lrelu(g_as1[s * NHEADS + h8] + ad8) - mx);
    }
    den += __shfl_xor_sync(0xFFFFFFFFu, den, 8);
    den += __shfl_xor_sync(0xFFFFFFFFu, den, 16);
    float inv = 1.f / fmaxf(den, 1e-16f);

    // remap to agg layout: lane covers columns of head hh = lane>>2.
    // head h stats live (replicated) in lanes with lane&7==h; take source lane hh (<8).
    int hh = lane >> 2;
    float mxh  = __shfl_sync(0xFFFFFFFFu, mx, hh);
    float invh = __shfl_sync(0xFFFFFFFFu, inv, hh);
    float adh  = __shfl_sync(0xFFFFFFFFu, ad8, hh);

    float ax = 0.f, ay = 0.f, az = 0.f, aw = 0.f;
#pragma unroll 2
    for (int j = beg; j < end; j++) {
        int s = g_csrc[j];
        float a = __expf(lrelu(g_as1[s * NHEADS + hh] + adh) - mxh) * invh;
        float4 t4 = *reinterpret_cast<const float4*>(g_t1 + (size_t)s * HD + lane * 4);
        ax += a * t4.x; ay += a * t4.y; az += a * t4.z; aw += a * t4.w;
    }
    float4 b4 = *reinterpret_cast<const float4*>(bias1 + lane * 4);
    float v0 = lrelu(ax + b4.x), v1 = lrelu(ay + b4.y);
    float v2 = lrelu(az + b4.z), v3 = lrelu(aw + b4.w);
    size_t base = (size_t)w * HD + lane * 4;
    __nv_bfloat16 h0 = __float2bfloat16(v0), h1 = __float2bfloat16(v1);
    __nv_bfloat16 h2 = __float2bfloat16(v2), h3 = __float2bfloat16(v3);
    __nv_bfloat162 ph0; ph0.x = h0; ph0.y = h1;
    __nv_bfloat162 ph1; ph1.x = h2; ph1.y = h3;
    __nv_bfloat162 pl0, pl1;
    pl0.x = __float2bfloat16(v0 - __bfloat162float(h0));
    pl0.y = __float2bfloat16(v1 - __bfloat162float(h1));
    pl1.x = __float2bfloat16(v2 - __bfloat162float(h2));
    pl1.y = __float2bfloat16(v3 - __bfloat162float(h3));
    *reinterpret_cast<__nv_bfloat162*>(g_o1h + base) = ph0;
    *reinterpret_cast<__nv_bfloat162*>(g_o1h + base + 2) = ph1;
    *reinterpret_cast<__nv_bfloat162*>(g_o1l + base) = pl0;
    *reinterpret_cast<__nv_bfloat162*>(g_o1l + base + 2) = pl1;
}

// ---------------- fused softmax + aggregation, conv2 (1 head) ----------------
__global__ void k_sagg2(const float* __restrict__ bias2) {
    int gt = blockIdx.x * blockDim.x + threadIdx.x;
    int w = gt >> 5, lane = gt & 31;
    if (w >= NN) return;
    int beg = g_rowptr[w], end = g_rowptr[w + 1];
    float ad = g_ad2[w];
    float mx = -INFINITY;
    for (int j = beg + lane; j < end; j += 32)
        mx = fmaxf(mx, lrelu(g_as2[g_csrc[j]] + ad));
#pragma unroll
    for (int off = 16; off; off >>= 1) mx = fmaxf(mx, __shfl_xor_sync(0xFFFFFFFFu, mx, off));
    float den = 0.f;
    for (int j = beg + lane; j < end; j += 32)
        den += __expf(lrelu(g_as2[g_csrc[j]] + ad) - mx);
#pragma unroll
    for (int off = 16; off; off >>= 1) den += __shfl_xor_sync(0xFFFFFFFFu, den, off);
    float inv = 1.f / fmaxf(den, 1e-16f);

    float ax = 0.f, ay = 0.f, az = 0.f, aw = 0.f;
#pragma unroll 2
    for (int j = beg; j < end; j++) {
        int s = g_csrc[j];
        float a = __expf(lrelu(g_as2[s] + ad) - mx) * inv;   // broadcast load
        float4 t4 = *reinterpret_cast<const float4*>(g_t2 + (size_t)s * HD + lane * 4);
        ax += a * t4.x; ay += a * t4.y; az += a * t4.z; aw += a * t4.w;
    }
    float4 b4 = *reinterpret_cast<const float4*>(bias2 + lane * 4);
    float4 o = make_float4(ax + b4.x, ay + b4.y, az + b4.z, aw + b4.w);
    *reinterpret_cast<float4*>(g_conv2 + (size_t)w * HD + lane * 4) = o;
}

// ---------------- final: BN2 apply + row L2 normalize ----------------
__global__ void k_final(float* __restrict__ out) {
    int gt = blockIdx.x * blockDim.x + threadIdx.x;
    int w = gt >> 5, lane = gt & 31;
    if (w >= NN) return;
    float4 h4 = *reinterpret_cast<const float4*>(g_h2 + (size_t)w * HD + lane * 4);
    float4 s4 = *reinterpret_cast<const float4*>(g_s2 + lane * 4);
    float4 sh4 = *reinterpret_cast<const float4*>(g_sh2 + lane * 4);
    float4 y;
    y.x = h4.x * s4.x + sh4.x; y.y = h4.y * s4.y + sh4.y;
    y.z = h4.z * s4.z + sh4.z; y.w = h4.w * s4.w + sh4.w;
    float ss = y.x * y.x + y.y * y.y + y.z * y.z + y.w * y.w;
#pragma unroll
    for (int off = 16; off; off >>= 1) ss += __shfl_xor_sync(0xFFFFFFFFu, ss, off);
    float inv = 1.f / fmaxf(sqrtf(ss), 1e-12f);
    y.x *= inv; y.y *= inv; y.z *= inv; y.w *= inv;
    *reinterpret_cast<float4*>(out + (size_t)w * HD + lane * 4) = y;
}

// ---------------- host launcher ----------------
extern "C" void kernel_launch(void* const* d_in, const int* in_sizes, int n_in,
                              void* d_out, int out_size) {
    const float* x        = (const float*)d_in[0];
    const float* W_in     = (const float*)d_in[1];
    const float* b_in     = (const float*)d_in[2];
    const float* gamma1   = (const float*)d_in[3];
    const float* beta1    = (const float*)d_in[4];
    const float* W1       = (const float*)d_in[5];
    const float* att_src1 = (const float*)d_in[6];
    const float* att_dst1 = (const float*)d_in[7];
    const float* bias1    = (const float*)d_in[8];
    const float* W2       = (const float*)d_in[9];
    const float* att_src2 = (const float*)d_in[10];
    const float* att_dst2 = (const float*)d_in[11];
    const float* bias2    = (const float*)d_in[12];
    const float* W_skip   = (const float*)d_in[13];
    const float* b_skip   = (const float*)d_in[14];
    const float* gamma2   = (const float*)d_in[15];
    const float* beta2    = (const float*)d_in[16];
    const void*  ei       = (const void*)d_in[17];
    float* out = (float*)d_out;

    __nv_bfloat16 *p_xh, *p_xl, *p_h0h, *p_h0l, *p_o1h, *p_o1l;
    __nv_bfloat16 *p_Winth, *p_Wintl, *p_W1th, *p_W1tl, *p_W2th, *p_W2tl, *p_Wsth, *p_Wstl;
    float *p_t1, *p_t2, *p_conv2, *p_h2, *p_W1p, *p_c1;
    float *p_bnsum1, *p_bnsq1, *p_bnsum2, *p_bnsq2;
    cudaGetSymbolAddress((void**)&p_xh, g_xh);
    cudaGetSymbolAddress((void**)&p_xl, g_xl);
    cudaGetSymbolAddress((void**)&p_h0h, g_h0h);
    cudaGetSymbolAddress((void**)&p_h0l, g_h0l);
    cudaGetSymbolAddress((void**)&p_o1h, g_o1h);
    cudaGetSymbolAddress((void**)&p_o1l, g_o1l);
    cudaGetSymbolAddress((void**)&p_Winth, g_Winth);
    cudaGetSymbolAddress((void**)&p_Wintl, g_Wintl);
    cudaGetSymbolAddress((void**)&p_W1th, g_W1th);
    cudaGetSymbolAddress((void**)&p_W1tl, g_W1tl);
    cudaGetSymbolAddress((void**)&p_W2th, g_W2th);
    cudaGetSymbolAddress((void**)&p_W2tl, g_W2tl);
    cudaGetSymbolAddress((void**)&p_Wsth, g_Wsth);
    cudaGetSymbolAddress((void**)&p_Wstl, g_Wstl);
    cudaGetSymbolAddress((void**)&p_t1, g_t1);
    cudaGetSymbolAddress((void**)&p_t2, g_t2);
    cudaGetSymbolAddress((void**)&p_conv2, g_conv2);
    cudaGetSymbolAddress((void**)&p_h2, g_h2);
    cudaGetSymbolAddress((void**)&p_W1p, g_W1p);
    cudaGetSymbolAddress((void**)&p_c1, g_c1);
    cudaGetSymbolAddress((void**)&p_bnsum1, g_bnsum1);
    cudaGetSymbolAddress((void**)&p_bnsq1, g_bnsq1);
    cudaGetSymbolAddress((void**)&p_bnsum2, g_bnsum2);
    cudaGetSymbolAddress((void**)&p_bnsq2, g_bnsq2);

    const int nb_edge = (EE + 255) / 256;
    const int nb_node = (NN * 32 + 255) / 256;
    const int gemm_grid = (NN + 127) / 128;

    k_detect<<<1, 1>>>(ei);
    k_zero<<<(NN + 255) / 256, 256>>>();
    k_count<<<nb_edge, 256>>>(ei);
    k_scanA<<<NSCAN, SCAN_BLK>>>();
    k_scanB<<<1, SCAN_BLK>>>();
    k_scanC<<<NSCAN, SCAN_BLK>>>();
    k_fill<<<nb_edge, 256>>>(ei);

    k_convA<<<(NN * IND / 4 + 255) / 256, 256>>>(x, p_xh, p_xl, NN * IND / 4);
    k_convW<<<HD, 256>>>(W_in, p_Winth, p_Wintl, IND);
    k_convW<<<HD, 256>>>(W2, p_W2th, p_W2tl, HD);
    k_convW<<<HD, 256>>>(W_skip, p_Wsth, p_Wstl, HD);

    // GEMM1: h0 = leaky(x @ W_in + b_in) -> bf16 pair, BN1 stats
    k_gemm_tc<IND, true, false, true, true><<<gemm_grid, 256>>>(
        p_xh, p_xl, p_Winth, p_Wintl, nullptr, p_h0h, p_h0l, b_in, nullptr, p_bnsum1, p_bnsq1);
    k_bnprep1<<<1, HD>>>(gamma1, beta1, W1);
    k_convW<<<HD, 256>>>(p_W1p, p_W1th, p_W1tl, HD);
    // GEMM2: t1 = h0 @ W1p + c1 (BN folded)
    k_gemm_tc<HD, false, false, false, false><<<gemm_grid, 256>>>(
        p_h0h, p_h0l, p_W1th, p_W1tl, p_t1, nullptr, nullptr, p_c1, nullptr, nullptr, nullptr);
    k_att1<<<nb_node, 256>>>(att_src1, att_dst1);
    k_sagg1<<<nb_node, 256>>>(bias1);
    // GEMM3: t2 = out1 @ W2
    k_gemm_tc<HD, false, false, false, false><<<gemm_grid, 256>>>(
        p_o1h, p_o1l, p_W2th, p_W2tl, p_t2, nullptr, nullptr, nullptr, nullptr, nullptr, nullptr);
    k_att2<<<nb_node, 256>>>(att_src2, att_dst2);
    k_sagg2<<<nb_node, 256>>>(bias2);
    // GEMM4: h2 = conv2 + out1 @ W_skip + b_skip, BN2 stats
    k_gemm_tc<HD, false, true, true, false><<<gemm_grid, 256>>>(
        p_o1h, p_o1l, p_Wsth, p_Wstl, p_h2, nullptr, nullptr, b_skip, p_conv2, p_bnsum2, p_bnsq2);
    k_bnprep2<<<1, HD>>>(gamma2, beta2);
    k_final<<<nb_node, 256>>>(out);
}

// round 12
// speedup vs baseline: 1.3319x; 1.0023x over previous
#include <cuda_runtime.h>
#include <cuda_bf16.h>
#include <stdint.h>
#include <math.h>

// ---------------- problem constants ----------------
#define NN 50000
#define EE 800000
#define IND 256
#define HD 128
#define NHEADS 8
#define SCAN_BLK 256
#define NSCAN ((NN + SCAN_BLK - 1) / SCAN_BLK)
#define AK 24   // smem bf16 row stride (48B)
// dynamic smem stage layout (elements): Ah 0, Al 3072, Bh 6144, Bl 9216; stage stride 12288
#define STG 12288
#define GEMM_DSMEM (2 * STG * 2)   // bytes = 49152
#define NEG_BIG (-1e30f)           // finite -inf sentinel: keeps online softmax NaN-free

// ---------------- scratch ----------------
__device__ __align__(16) __nv_bfloat16 g_xh[(size_t)NN * IND], g_xl[(size_t)NN * IND];
__device__ __align__(16) __nv_bfloat16 g_h0h[NN * HD], g_h0l[NN * HD];
__device__ __align__(16) __nv_bfloat16 g_o1h[NN * HD], g_o1l[NN * HD];
__device__ __align__(16) __nv_bfloat16 g_Winth[HD * IND], g_Wintl[HD * IND];
__device__ __align__(16) __nv_bfloat16 g_W1th[HD * HD], g_W1tl[HD * HD];
__device__ __align__(16) __nv_bfloat16 g_W2th[HD * HD], g_W2tl[HD * HD];
__device__ __align__(16) __nv_bfloat16 g_Wsth[HD * HD], g_Wstl[HD * HD];
__device__ __align__(16) float g_t1[NN * HD];
__device__ __align__(16) float g_t2[NN * HD];
__device__ __align__(16) float g_conv2[NN * HD];
__device__ __align__(16) float g_h2[NN * HD];
__device__ __align__(16) float g_as1[NN * NHEADS], g_ad1[NN * NHEADS];
__device__ __align__(16) float g_as2[NN], g_ad2[NN];
__device__ __align__(16) int   g_cnt[NN];
__device__ __align__(16) int   g_scantmp[NN];
__device__ __align__(16) int   g_blksum[SCAN_BLK];
__device__ __align__(16) int   g_blkoff[SCAN_BLK];
__device__ int   g_total;
__device__ __align__(16) int   g_rowptr[NN + 1];
__device__ __align__(16) int   g_cursor[NN];
__device__ __align__(16) int   g_csrc[EE];
__device__ __align__(16) float g_bnsum1[HD], g_bnsq1[HD], g_bnsum2[HD], g_bnsq2[HD];
__device__ __align__(16) float g_scale1[HD], g_shift1[HD];
__device__ __align__(16) float g_W1p[HD * HD], g_c1[HD];
__device__ int g_is64;

__device__ __forceinline__ float lrelu(float v) { return v >= 0.f ? v : 0.2f * v; }

__device__ __forceinline__ int edge_idx(const void* ei, long long pos) {
    if (g_is64) return (int)((const long long*)ei)[pos];
    return ((const int*)ei)[pos];
}

// ---------------- dtype detection (warp-parallel) ----------------
__global__ void k_detect(const void* ei) {
    const long long* q = (const long long*)ei;
    int lane = threadIdx.x;
    long long v0 = q[lane], v1 = q[lane + 32];
    int ok = (v0 >= 0 && v0 < NN && v1 >= 0 && v1 < NN);
    unsigned m = __ballot_sync(0xFFFFFFFFu, ok);
    if (lane == 0) g_is64 = (m == 0xFFFFFFFFu);
}

// ---------------- zero ----------------
__global__ void k_zero() {
    int i = blockIdx.x * blockDim.x + threadIdx.x;
    if (i < NN) g_cnt[i] = 0;
    if (i < HD) { g_bnsum1[i] = 0.f; g_bnsq1[i] = 0.f; g_bnsum2[i] = 0.f; g_bnsq2[i] = 0.f; }
}

// ---------------- CSR build ----------------
__global__ void k_count(const void* __restrict__ ei) {
    int e = blockIdx.x * blockDim.x + threadIdx.x;
    if (e < EE) {
        int d = edge_idx(ei, (long long)EE + e);
        if (d >= 0 && d < NN) atomicAdd(&g_cnt[d], 1);
    }
}

__global__ void k_scanA() {
    __shared__ int sh[SCAN_BLK];
    int tid = threadIdx.x;
    int i = blockIdx.x * SCAN_BLK + tid;
    int v = (i < NN) ? g_cnt[i] : 0;
    sh[tid] = v;
    __syncthreads();
#pragma unroll
    for (int off = 1; off < SCAN_BLK; off <<= 1) {
        int t = (tid >= off) ? sh[tid - off] : 0;
        __syncthreads();
        sh[tid] += t;
        __syncthreads();
    }
    if (i < NN) g_scantmp[i] = sh[tid];
    if (tid == SCAN_BLK - 1) g_blksum[blockIdx.x] = sh[tid];
}

__global__ void k_scanB() {
    __shared__ int sh[SCAN_BLK];
    int tid = threadIdx.x;
    int v = (tid < NSCAN) ? g_blksum[tid] : 0;
    sh[tid] = v;
    __syncthreads();
#pragma unroll
    for (int off = 1; off < SCAN_BLK; off <<= 1) {
        int t = (tid >= off) ? sh[tid - off] : 0;
        __syncthreads();
        sh[tid] += t;
        __syncthreads();
    }
    g_blkoff[tid] = sh[tid] - v;
    if (tid == SCAN_BLK - 1) g_total = sh[tid];
}

__global__ void k_scanC() {
    int i = blockIdx.x * blockDim.x + threadIdx.x;
    if (i < NN) {
        int r = g_blkoff[blockIdx.x] + g_scantmp[i] - g_cnt[i];
        g_rowptr[i] = r;
        g_cursor[i] = r;
    }
    if (i == 0) g_rowptr[NN] = g_total;
}

__global__ void k_fill(const void* __restrict__ ei) {
    int e = blockIdx.x * blockDim.x + threadIdx.x;
    if (e < EE) {
        int s = edge_idx(ei, e);
        int d = edge_idx(ei, (long long)EE + e);
        if (d >= 0 && d < NN && s >= 0 && s < NN) {
            int p = atomicAdd(&g_cursor[d], 1);
            if (p >= 0 && p < EE) g_csrc[p] = s;
        }
    }
}

// ---------------- fp32 -> bf16 hi/lo streaming split ----------------
__global__ void k_convA(const float* __restrict__ src, __nv_bfloat16* __restrict__ dh,
                        __nv_bfloat16* __restrict__ dl, int n4) {
    int i = blockIdx.x * blockDim.x + threadIdx.x;
    if (i >= n4) return;
    float4 v = *reinterpret_cast<const float4*>(src + (size_t)i * 4);
    __nv_bfloat16 h0 = __float2bfloat16(v.x), h1 = __float2bfloat16(v.y);
    __nv_bfloat16 h2 = __float2bfloat16(v.z), h3 = __float2bfloat16(v.w);
    __nv_bfloat162 ph0; ph0.x = h0; ph0.y = h1;
    __nv_bfloat162 ph1; ph1.x = h2; ph1.y = h3;
    __nv_bfloat162 pl0, pl1;
    pl0.x = __float2bfloat16(v.x - __bfloat162float(h0));
    pl0.y = __float2bfloat16(v.y - __bfloat162float(h1));
    pl1.x = __float2bfloat16(v.z - __bfloat162float(h2));
    pl1.y = __float2bfloat16(v.w - __bfloat162float(h3));
    *reinterpret_cast<__nv_bfloat162*>(dh + (size_t)i * 4) = ph0;
    *reinterpret_cast<__nv_bfloat162*>(dh + (size_t)i * 4 + 2) = ph1;
    *reinterpret_cast<__nv_bfloat162*>(dl + (size_t)i * 4) = pl0;
    *reinterpret_cast<__nv_bfloat162*>(dl + (size_t)i * 4 + 2) = pl1;
}

__global__ void k_convW(const float* __restrict__ W, __nv_bfloat16* __restrict__ dh,
                        __nv_bfloat16* __restrict__ dl, int K) {
    int n = blockIdx.x;
    for (int k = threadIdx.x; k < K; k += blockDim.x) {
        float v = W[(size_t)k * HD + n];
        __nv_bfloat16 h = __float2bfloat16(v);
        dh[(size_t)n * K + k] = h;
        dl[(size_t)n * K + k] = __float2bfloat16(v - __bfloat162float(h));
    }
}

// two HD x HD weights in one launch (grid 256)
__global__ void k_convW2(const float* __restrict__ Wa, __nv_bfloat16* __restrict__ dha,
                         __nv_bfloat16* __restrict__ dla,
                         const float* __restrict__ Wb, __nv_bfloat16* __restrict__ dhb,
                         __nv_bfloat16* __restrict__ dlb) {
    int b = blockIdx.x;
    const float* W = (b < HD) ? Wa : Wb;
    __nv_bfloat16* dh = (b < HD) ? dha : dhb;
    __nv_bfloat16* dl = (b < HD) ? dla : dlb;
    int n = b & (HD - 1);
    for (int k = threadIdx.x; k < HD; k += blockDim.x) {
        float v = W[(size_t)k * HD + n];
        __nv_bfloat16 h = __float2bfloat16(v);
        dh[(size_t)n * HD + k] = h;
        dl[(size_t)n * HD + k] = __float2bfloat16(v - __bfloat162float(h));
    }
}

// ---------------- split-bf16 tensor-core GEMM (double-buffered) ----------------
__device__ __forceinline__ void mma16816(float* c, const uint32_t* a, uint32_t b0, uint32_t b1) {
    asm volatile(
        "mma.sync.aligned.m16n8k16.row.col.f32.bf16.bf16.f32 "
        "{%0,%1,%2,%3}, {%4,%5,%6,%7}, {%8,%9}, {%0,%1,%2,%3};"
        : "+f"(c[0]), "+f"(c[1]), "+f"(c[2]), "+f"(c[3])
        : "r"(a[0]), "r"(a[1]), "r"(a[2]), "r"(a[3]), "r"(b0), "r"(b1));
}

template <int K, bool LEAKY, bool ADDM, bool STATS, bool OUTBF>
__global__ void __launch_bounds__(256, 2) k_gemm_tc(
        const __nv_bfloat16* __restrict__ Ahg, const __nv_bfloat16* __restrict__ Alg,
        const __nv_bfloat16* __restrict__ Bhg, const __nv_bfloat16* __restrict__ Blg,
        float* __restrict__ C, __nv_bfloat16* __restrict__ Ch, __nv_bfloat16* __restrict__ Cl,
        const float* __restrict__ bias, const float* __restrict__ addm,
        float* __restrict__ bnsum, float* __restrict__ bnsq) {
    extern __shared__ __nv_bfloat16 dyn[];
    __shared__ float s_sum[128], s_sq[128];
    const int tid = threadIdx.x;
    const int m0 = blockIdx.x * 128;
    if (STATS && tid < 128) { s_sum[tid] = 0.f; s_sq[tid] = 0.f; }
    const int lane = tid & 31;
    const int wid = tid >> 5;
    const int g = lane >> 2, r = lane & 3;
    const int wm = (wid & 3) * 32;
    const int wn = (wid >> 2) * 64;

    float acc[2][8][4];
#pragma unroll
    for (int i = 0; i < 2; i++)
#pragma unroll
        for (int j = 0; j < 8; j++)
#pragma unroll
            for (int q = 0; q < 4; q++) acc[i][j][q] = 0.f;

    const int row = tid >> 1;
    const int koff = (tid & 1) * 8;
    const bool arow_ok = (m0 + row) < NN;
    const size_t abase = (size_t)(m0 + row) * K;
    const size_t bbase = (size_t)row * K;

    uint4 rah, ral, rbh, rbl;
    const uint4 z4 = make_uint4(0, 0, 0, 0);

    // stage 0 preload + store
    rah = arow_ok ? *reinterpret_cast<const uint4*>(Ahg + abase + koff) : z4;
    ral = arow_ok ? *reinterpret_cast<const uint4*>(Alg + abase + koff) : z4;
    rbh = *reinterpret_cast<const uint4*>(Bhg + bbase + koff);
    rbl = *reinterpret_cast<const uint4*>(Blg + bbase + koff);
    {
        __nv_bfloat16* st = dyn;   // stage 0
        *reinterpret_cast<uint4*>(&st[row * AK + koff])        = rah;
        *reinterpret_cast<uint4*>(&st[3072 + row * AK + koff]) = ral;
        *reinterpret_cast<uint4*>(&st[6144 + row * AK + koff]) = rbh;
        *reinterpret_cast<uint4*>(&st[9216 + row * AK + koff]) = rbl;
    }
    __syncthreads();

    constexpr int NC = K / 16;
#pragma unroll 2
    for (int c = 0; c < NC; c++) {
        const int cur = c & 1;
        __nv_bfloat16* Ahs = dyn + cur * STG;
        __nv_bfloat16* Als = Ahs + 3072;
        __nv_bfloat16* Bhs = Ahs + 6144;
        __nv_bfloat16* Bls = Ahs + 9216;
        const bool more = (c + 1 < NC);
        if (more) {
            int k0 = (c + 1) * 16;
            rah = arow_ok ? *reinterpret_cast<const uint4*>(Ahg + abase + k0 + koff) : z4;
            ral = arow_ok ? *reinterpret_cast<const uint4*>(Alg + abase + k0 + koff) : z4;
            rbh = *reinterpret_cast<const uint4*>(Bhg + bbase + k0 + koff);
            rbl = *reinterpret_cast<const uint4*>(Blg + bbase + k0 + koff);
        }
        // fragments + MMA (indexing identical to proven layout)
        uint32_t ah[2][4], al[2][4];
#pragma unroll
        for (int mi = 0; mi < 2; mi++) {
            int mr = wm + mi * 16;
            ah[mi][0] = *(const uint32_t*)&Ahs[(mr + g) * AK + 2 * r];
            ah[mi][1] = *(const uint32_t*)&Ahs[(mr + g + 8) * AK + 2 * r];
            ah[mi][2] = *(const uint32_t*)&Ahs[(mr + g) * AK + 2 * r + 8];
            ah[mi][3] = *(const uint32_t*)&Ahs[(mr + g + 8) * AK + 2 * r + 8];
            al[mi][0] = *(const uint32_t*)&Als[(mr + g) * AK + 2 * r];
            al[mi][1] = *(const uint32_t*)&Als[(mr + g + 8) * AK + 2 * r];
            al[mi][2] = *(const uint32_t*)&Als[(mr + g) * AK + 2 * r + 8];
            al[mi][3] = *(const uint32_t*)&Als[(mr + g + 8) * AK + 2 * r + 8];
        }
#pragma unroll
        for (int ni = 0; ni < 8; ni++) {
            int nr = (wn + ni * 8 + g) * AK;
            uint32_t bh0 = *(const uint32_t*)&Bhs[nr + 2 * r];
            uint32_t bh1 = *(const uint32_t*)&Bhs[nr + 2 * r + 8];
            uint32_t bl0 = *(const uint32_t*)&Bls[nr + 2 * r];
            uint32_t bl1 = *(const uint32_t*)&Bls[nr + 2 * r + 8];
#pragma unroll
            for (int mi = 0; mi < 2; mi++) {
                mma16816(acc[mi][ni], al[mi], bh0, bh1);
                mma16816(acc[mi][ni], ah[mi], bl0, bl1);
                mma16816(acc[mi][ni], ah[mi], bh0, bh1);
            }
        }
        if (more) {
            __nv_bfloat16* st = dyn + (cur ^ 1) * STG;
            *reinterpret_cast<uint4*>(&st[row * AK + koff])        = rah;
            *reinterpret_cast<uint4*>(&st[3072 + row * AK + koff]) = ral;
            *reinterpret_cast<uint4*>(&st[6144 + row * AK + koff]) = rbh;
            *reinterpret_cast<uint4*>(&st[9216 + row * AK + koff]) = rbl;
        }
        __syncthreads();
    }

    // ---- epilogue ----
#pragma unroll
    for (int mi = 0; mi < 2; mi++) {
#pragma unroll
        for (int ni = 0; ni < 8; ni++) {
            int mA = m0 + wm + mi * 16 + g;
            int mB = mA + 8;
            int n = wn + ni * 8 + 2 * r;
            float bc0 = bias ? bias[n] : 0.f;
            float bc1 = bias ? bias[n + 1] : 0.f;
            float v0 = acc[mi][ni][0] + bc0, v1 = acc[mi][ni][1] + bc1;
            float v2 = acc[mi][ni][2] + bc0, v3 = acc[mi][ni][3] + bc1;
            bool okA = mA < NN, okB = mB < NN;
            if (okA) {
                if (ADDM) { v0 += addm[(size_t)mA * HD + n]; v1 += addm[(size_t)mA * HD + n + 1]; }
                if (LEAKY) { v0 = lrelu(v0); v1 = lrelu(v1); }
                if (OUTBF) {
                    __nv_bfloat16 h0 = __float2bfloat16(v0), h1 = __float2bfloat16(v1);
                    __nv_bfloat162 ph; ph.x = h0; ph.y = h1;
                    __nv_bfloat162 pl;
                    pl.x = __float2bfloat16(v0 - __bfloat162float(h0));
                    pl.y = __float2bfloat16(v1 - __bfloat162float(h1));
                    *reinterpret_cast<__nv_bfloat162*>(Ch + (size_t)mA * HD + n) = ph;
                    *reinterpret_cast<__nv_bfloat162*>(Cl + (size_t)mA * HD + n) = pl;
                } else {
                    *(float2*)&C[(size_t)mA * HD + n] = make_float2(v0, v1);
                }
            }
            if (okB) {
                if (ADDM) { v2 += addm[(size_t)mB * HD + n]; v3 += addm[(size_t)mB * HD + n + 1]; }
                if (LEAKY) { v2 = lrelu(v2); v3 = lrelu(v3); }
                if (OUTBF) {
                    __nv_bfloat16 h2 = __float2bfloat16(v2), h3 = __float2bfloat16(v3);
                    __nv_bfloat162 ph; ph.x = h2; ph.y = h3;
                    __nv_bfloat162 pl;
                    pl.x = __float2bfloat16(v2 - __bfloat162float(h2));
                    pl.y = __float2bfloat16(v3 - __bfloat162float(h3));
                    *reinterpret_cast<__nv_bfloat162*>(Ch + (size_t)mB * HD + n) = ph;
                    *reinterpret_cast<__nv_bfloat162*>(Cl + (size_t)mB * HD + n) = pl;
                } else {
                    *(float2*)&C[(size_t)mB * HD + n] = make_float2(v2, v3);
                }
            }
            if (STATS && (okA || okB)) {
                float s0 = (okA ? v0 : 0.f) + (okB ? v2 : 0.f);
                float s1 = (okA ? v1 : 0.f) + (okB ? v3 : 0.f);
                float q0 = (okA ? v0 * v0 : 0.f) + (okB ? v2 * v2 : 0.f);
                float q1 = (okA ? v1 * v1 : 0.f) + (okB ? v3 * v3 : 0.f);
                atomicAdd(&s_sum[n], s0);
                atomicAdd(&s_sum[n + 1], s1);
                atomicAdd(&s_sq[n], q0);
                atomicAdd(&s_sq[n + 1], q1);
            }
        }
    }
    if (STATS) {
        __syncthreads();
        if (tid < 128) {
            atomicAdd(&bnsum[tid], s_sum[tid]);
            atomicAdd(&bnsq[tid], s_sq[tid]);
        }
    }
}

// ---------------- BN1 prep ----------------
__global__ void k_bnprep1(const float* __restrict__ gamma1, const float* __restrict__ beta1,
                          const float* __restrict__ W1) {
    int c = threadIdx.x;
    float mean = g_bnsum1[c] / (float)NN;
    float var = g_bnsq1[c] / (float)NN - mean * mean;
    float sc = gamma1[c] * rsqrtf(var + 1e-5f);
    float sh = beta1[c] - mean * sc;
    g_scale1[c] = sc;
    g_shift1[c] = sh;
    __syncthreads();
    float cj = 0.f;
    for (int k = 0; k < HD; k++) {
        cj += g_shift1[k] * W1[k * HD + c];
        g_W1p[k * HD + c] = g_scale1[k] * W1[k * HD + c];
    }
    g_c1[c] = cj;
}

// ---------------- attention coefficients ----------------
__global__ void k_att1(const float* __restrict__ att_src, const float* __restrict__ att_dst) {
    int gt = blockIdx.x * blockDim.x + threadIdx.x;
    int w = gt >> 5, lane = gt & 31;
    if (w >= NN) return;
    float4 t4 = *reinterpret_cast<const float4*>(g_t1 + (size_t)w * HD + lane * 4);
    float4 s4 = *reinterpret_cast<const float4*>(att_src + lane * 4);
    float4 d4 = *reinterpret_cast<const float4*>(att_dst + lane * 4);
    float ps = t4.x * s4.x + t4.y * s4.y + t4.z * s4.z + t4.w * s4.w;
    float pd = t4.x * d4.x + t4.y * d4.y + t4.z * d4.z + t4.w * d4.w;
    ps += __shfl_xor_sync(0xFFFFFFFFu, ps, 1); ps += __shfl_xor_sync(0xFFFFFFFFu, ps, 2);
    pd += __shfl_xor_sync(0xFFFFFFFFu, pd, 1); pd += __shfl_xor_sync(0xFFFFFFFFu, pd, 2);
    if ((lane & 3) == 0) {
        g_as1[w * NHEADS + (lane >> 2)] = ps;
        g_ad1[w * NHEADS + (lane >> 2)] = pd;
    }
}

__global__ void k_att2(const float* __restrict__ att_src, const float* __restrict__ att_dst) {
    int gt = blockIdx.x * blockDim.x + threadIdx.x;
    int w = gt >> 5, lane = gt & 31;
    if (w >= NN) return;
    float4 t4 = *reinterpret_cast<const float4*>(g_t2 + (size_t)w * HD + lane * 4);
    float4 s4 = *reinterpret_cast<const float4*>(att_src + lane * 4);
    float4 d4 = *reinterpret_cast<const float4*>(att_dst + lane * 4);
    float ps = t4.x * s4.x + t4.y * s4.y + t4.z * s4.z + t4.w * s4.w;
    float pd = t4.x * d4.x + t4.y * d4.y + t4.z * d4.z + t4.w * d4.w;
#pragma unroll
    for (int off = 16; off; off >>= 1) {
        ps += __shfl_xor_sync(0xFFFFFFFFu, ps, off);
        pd += __shfl_xor_sync(0xFFFFFFFFu, pd, off);
    }
    if (lane == 0) { g_as2[w] = ps; g_ad2[w] = pd; }
}

// online-softmax combine (NaN-free as long as inputs are finite — use NEG_BIG sentinel)
__device__ __forceinline__ void sm_merge(float& mx, float& den, float omx, float oden) {
    float nm = fmaxf(mx, omx);
    den = den * __expf(mx - nm) + oden * __expf(omx - nm);
    mx = nm;
}

// ---------------- fused softmax + aggregation, conv1 ----------------
__global__ void k_sagg1(const float* __restrict__ bias1) {
    int gt = blockIdx.x * blockDim.x + threadIdx.x;
    int w = gt >> 5, lane = gt & 31;
    if (w >= NN) return;
    int beg = g_rowptr[w], end = g_rowptr[w + 1];

    // single-pass online softmax stats: head h8 = lane&7, edge slot es = lane>>3
    int h8 = lane & 7, es = lane >> 3;
    float ad8 = g_ad1[w * NHEADS + h8];
    float mx = NEG_BIG, den = 0.f;
    for (int j = beg + es; j < end; j += 4) {
        int s = g_csrc[j];
        float v = lrelu(g_as1[s * NHEADS + h8] + ad8);
        float nm = fmaxf(mx, v);
        den = den * __expf(mx - nm) + __expf(v - nm);
        mx = nm;
    }
    sm_merge(mx, den, __shfl_xor_sync(0xFFFFFFFFu, mx, 8),  __shfl_xor_sync(0xFFFFFFFFu, den, 8));
    sm_merge(mx, den, __shfl_xor_sync(0xFFFFFFFFu, mx, 16), __shfl_xor_sync(0xFFFFFFFFu, den, 16));
    float inv = 1.f / fmaxf(den, 1e-16f);

    // remap to agg layout: lane covers columns of head hh = lane>>2
    int hh = lane >> 2;
    float mxh  = __shfl_sync(0xFFFFFFFFu, mx, hh);
    float invh = __shfl_sync(0xFFFFFFFFu, inv, hh);
    float adh  = __shfl_sync(0xFFFFFFFFu, ad8, hh);

    float ax = 0.f, ay = 0.f, az = 0.f, aw = 0.f;
#pragma unroll 2
    for (int j = beg; j < end; j++) {
        int s = g_csrc[j];
        float a = __expf(lrelu(g_as1[s * NHEADS + hh] + adh) - mxh) * invh;
        float4 t4 = *reinterpret_cast<const float4*>(g_t1 + (size_t)s * HD + lane * 4);
        ax += a * t4.x; ay += a * t4.y; az += a * t4.z; aw += a * t4.w;
    }
    float4 b4 = *reinterpret_cast<const float4*>(bias1 + lane * 4);
    float v0 = lrelu(ax + b4.x), v1 = lrelu(ay + b4.y);
    float v2 = lrelu(az + b4.z), v3 = lrelu(aw + b4.w);
    size_t base = (size_t)w * HD + lane * 4;
    __nv_bfloat16 h0 = __float2bfloat16(v0), h1 = __float2bfloat16(v1);
    __nv_bfloat16 h2 = __float2bfloat16(v2), h3 = __float2bfloat16(v3);
    __nv_bfloat162 ph0; ph0.x = h0; ph0.y = h1;
    __nv_bfloat162 ph1; ph1.x = h2; ph1.y = h3;
    __nv_bfloat162 pl0, pl1;
    pl0.x = __float2bfloat16(v0 - __bfloat162float(h0));
    pl0.y = __float2bfloat16(v1 - __bfloat162float(h1));
    pl1.x = __float2bfloat16(v2 - __bfloat162float(h2));
    pl1.y = __float2bfloat16(v3 - __bfloat162float(h3));
    *reinterpret_cast<__nv_bfloat162*>(g_o1h + base) = ph0;
    *reinterpret_cast<__nv_bfloat162*>(g_o1h + base + 2) = ph1;
    *reinterpret_cast<__nv_bfloat162*>(g_o1l + base) = pl0;
    *reinterpret_cast<__nv_bfloat162*>(g_o1l + base + 2) = pl1;
}

// ---------------- fused softmax + aggregation, conv2 ----------------
__global__ void k_sagg2(const float* __restrict__ bias2) {
    int gt = blockIdx.x * blockDim.x + threadIdx.x;
    int w = gt >> 5, lane = gt & 31;
    if (w >= NN) return;
    int beg = g_rowptr[w], end = g_rowptr[w + 1];
    float ad = g_ad2[w];
    float mx = NEG_BIG, den = 0.f;
    for (int j = beg + lane; j < end; j += 32) {
        float v = lrelu(g_as2[g_csrc[j]] + ad);
        float nm = fmaxf(mx, v);
        den = den * __expf(mx - nm) + __expf(v - nm);
        mx = nm;
    }
#pragma unroll
    for (int off = 16; off; off >>= 1)
        sm_merge(mx, den, __shfl_xor_sync(0xFFFFFFFFu, mx, off), __shfl_xor_sync(0xFFFFFFFFu, den, off));
    float inv = 1.f / fmaxf(den, 1e-16f);

    float ax = 0.f, ay = 0.f, az = 0.f, aw = 0.f;
#pragma unroll 2
    for (int j = beg; j < end; j++) {
        int s = g_csrc[j];
        float a = __expf(lrelu(g_as2[s] + ad) - mx) * inv;
        float4 t4 = *reinterpret_cast<const float4*>(g_t2 + (size_t)s * HD + lane * 4);
        ax += a * t4.x; ay += a * t4.y; az += a * t4.z; aw += a * t4.w;
    }
    float4 b4 = *reinterpret_cast<const float4*>(bias2 + lane * 4);
    float4 o = make_float4(ax + b4.x, ay + b4.y, az + b4.z, aw + b4.w);
    *reinterpret_cast<float4*>(g_conv2 + (size_t)w * HD + lane * 4) = o;
}

// ---------------- final: BN2 (inline) + row L2 normalize ----------------
__global__ void k_final(float* __restrict__ out, const float* __restrict__ gamma2,
                        const float* __restrict__ beta2) {
    int gt = blockIdx.x * blockDim.x + threadIdx.x;
    int w = gt >> 5, lane = gt & 31;
    if (w >= NN) return;
    int c = lane * 4;
    float4 sum4 = *reinterpret_cast<const float4*>(g_bnsum2 + c);
    float4 sq4  = *reinterpret_cast<const float4*>(g_bnsq2 + c);
    float4 gm4  = *reinterpret_cast<const float4*>(gamma2 + c);
    float4 bt4  = *reinterpret_cast<const float4*>(beta2 + c);
    const float invN = 1.f / (float)NN;
    float m0 = sum4.x * invN, m1 = sum4.y * invN, m2 = sum4.z * invN, m3 = sum4.w * invN;
    float sc0 = gm4.x * rsqrtf(sq4.x * invN - m0 * m0 + 1e-5f);
    float sc1 = gm4.y * rsqrtf(sq4.y * invN - m1 * m1 + 1e-5f);
    float sc2 = gm4.z * rsqrtf(sq4.z * invN - m2 * m2 + 1e-5f);
    float sc3 = gm4.w * rsqrtf(sq4.w * invN - m3 * m3 + 1e-5f);
    float sh0 = bt4.x - m0 * sc0, sh1 = bt4.y - m1 * sc1;
    float sh2 = bt4.z - m2 * sc2, sh3 = bt4.w - m3 * sc3;

    float4 h4 = *reinterpret_cast<const float4*>(g_h2 + (size_t)w * HD + c);
    float4 y;
    y.x = h4.x * sc0 + sh0; y.y = h4.y * sc1 + sh1;
    y.z = h4.z * sc2 + sh2; y.w = h4.w * sc3 + sh3;
    float ss = y.x * y.x + y.y * y.y + y.z * y.z + y.w * y.w;
#pragma unroll
    for (int off = 16; off; off >>= 1) ss += __shfl_xor_sync(0xFFFFFFFFu, ss, off);
    float inv = 1.f / fmaxf(sqrtf(ss), 1e-12f);
    y.x *= inv; y.y *= inv; y.z *= inv; y.w *= inv;
    *reinterpret_cast<float4*>(out + (size_t)w * HD + c) = y;
}

// ---------------- host launcher ----------------
extern "C" void kernel_launch(void* const* d_in, const int* in_sizes, int n_in,
                              void* d_out, int out_size) {
    const float* x        = (const float*)d_in[0];
    const float* W_in     = (const float*)d_in[1];
    const float* b_in     = (const float*)d_in[2];
    const float* gamma1   = (const float*)d_in[3];
    const float* beta1    = (const float*)d_in[4];
    const float* W1       = (const float*)d_in[5];
    const float* att_src1 = (const float*)d_in[6];
    const float* att_dst1 = (const float*)d_in[7];
    const float* bias1    = (const float*)d_in[8];
    const float* W2       = (const float*)d_in[9];
    const float* att_src2 = (const float*)d_in[10];
    const float* att_dst2 = (const float*)d_in[11];
    const float* bias2    = (const float*)d_in[12];
    const float* W_skip   = (const float*)d_in[13];
    const float* b_skip   = (const float*)d_in[14];
    const float* gamma2   = (const float*)d_in[15];
    const float* beta2    = (const float*)d_in[16];
    const void*  ei       = (const void*)d_in[17];
    float* out = (float*)d_out;

    __nv_bfloat16 *p_xh, *p_xl, *p_h0h, *p_h0l, *p_o1h, *p_o1l;
    __nv_bfloat16 *p_Winth, *p_Wintl, *p_W1th, *p_W1tl, *p_W2th, *p_W2tl, *p_Wsth, *p_Wstl;
    float *p_t1, *p_t2, *p_conv2, *p_h2, *p_W1p, *p_c1;
    float *p_bnsum1, *p_bnsq1, *p_bnsum2, *p_bnsq2;
    cudaGetSymbolAddress((void**)&p_xh, g_xh);
    cudaGetSymbolAddress((void**)&p_xl, g_xl);
    cudaGetSymbolAddress((void**)&p_h0h, g_h0h);
    cudaGetSymbolAddress((void**)&p_h0l, g_h0l);
    cudaGetSymbolAddress((void**)&p_o1h, g_o1h);
    cudaGetSymbolAddress((void**)&p_o1l, g_o1l);
    cudaGetSymbolAddress((void**)&p_Winth, g_Winth);
    cudaGetSymbolAddress((void**)&p_Wintl, g_Wintl);
    cudaGetSymbolAddress((void**)&p_W1th, g_W1th);
    cudaGetSymbolAddress((void**)&p_W1tl, g_W1tl);
    cudaGetSymbolAddress((void**)&p_W2th, g_W2th);
    cudaGetSymbolAddress((void**)&p_W2tl, g_W2tl);
    cudaGetSymbolAddress((void**)&p_Wsth, g_Wsth);
    cudaGetSymbolAddress((void**)&p_Wstl, g_Wstl);
    cudaGetSymbolAddress((void**)&p_t1, g_t1);
    cudaGetSymbolAddress((void**)&p_t2, g_t2);
    cudaGetSymbolAddress((void**)&p_conv2, g_conv2);
    cudaGetSymbolAddress((void**)&p_h2, g_h2);
    cudaGetSymbolAddress((void**)&p_W1p, g_W1p);
    cudaGetSymbolAddress((void**)&p_c1, g_c1);
    cudaGetSymbolAddress((void**)&p_bnsum1, g_bnsum1);
    cudaGetSymbolAddress((void**)&p_bnsq1, g_bnsq1);
    cudaGetSymbolAddress((void**)&p_bnsum2, g_bnsum2);
    cudaGetSymbolAddress((void**)&p_bnsq2, g_bnsq2);

    // opt-in to 48KB dynamic smem (host-side attribute set; idempotent, not captured)
    cudaFuncSetAttribute(k_gemm_tc<IND, true, false, true, true>,
                         cudaFuncAttributeMaxDynamicSharedMemorySize, GEMM_DSMEM);
    cudaFuncSetAttribute(k_gemm_tc<HD, false, false, false, false>,
                         cudaFuncAttributeMaxDynamicSharedMemorySize, GEMM_DSMEM);
    cudaFuncSetAttribute(k_gemm_tc<HD, false, true, true, false>,
                         cudaFuncAttributeMaxDynamicSharedMemorySize, GEMM_DSMEM);

    const int nb_edge = (EE + 255) / 256;
    const int nb_node = (NN * 32 + 255) / 256;
    const int gemm_grid = (NN + 127) / 128;

    k_detect<<<1, 32>>>(ei);
    k_zero<<<(NN + 255) / 256, 256>>>();
    k_count<<<nb_edge, 256>>>(ei);
    k_scanA<<<NSCAN, SCAN_BLK>>>();
    k_scanB<<<1, SCAN_BLK>>>();
    k_scanC<<<NSCAN, SCAN_BLK>>>();
    k_fill<<<nb_edge, 256>>>(ei);

    k_convA<<<(NN * IND / 4 + 255) / 256, 256>>>(x, p_xh, p_xl, NN * IND / 4);
    k_convW<<<HD, 256>>>(W_in, p_Winth, p_Wintl, IND);
    k_convW2<<<2 * HD, 128>>>(W2, p_W2th, p_W2tl, W_skip, p_Wsth, p_Wstl);

    // GEMM1: h0 = leaky(x @ W_in + b_in) -> bf16 pair, BN1 stats
    k_gemm_tc<IND, true, false, true, true><<<gemm_grid, 256, GEMM_DSMEM>>>(
        p_xh, p_xl, p_Winth, p_Wintl, nullptr, p_h0h, p_h0l, b_in, nullptr, p_bnsum1, p_bnsq1);
    k_bnprep1<<<1, HD>>>(gamma1, beta1, W1);
    k_convW<<<HD, 256>>>(p_W1p, p_W1th, p_W1tl, HD);
    // GEMM2: t1 = h0 @ W1p + c1 (BN folded)
    k_gemm_tc<HD, false, false, false, false><<<gemm_grid, 256, GEMM_DSMEM>>>(
        p_h0h, p_h0l, p_W1th, p_W1tl, p_t1, nullptr, nullptr, p_c1, nullptr, nullptr, nullptr);
    k_att1<<<nb_node, 256>>>(att_src1, att_dst1);
    k_sagg1<<<nb_node, 256>>>(bias1);
    // GEMM3: t2 = out1 @ W2
    k_gemm_tc<HD, false, false, false, false><<<gemm_grid, 256, GEMM_DSMEM>>>(
        p_o1h, p_o1l, p_W2th, p_W2tl, p_t2, nullptr, nullptr, nullptr, nullptr, nullptr, nullptr);
    k_att2<<<nb_node, 256>>>(att_src2, att_dst2);
    k_sagg2<<<nb_node, 256>>>(bias2);
    // GEMM4: h2 = conv2 + out1 @ W_skip + b_skip, BN2 stats
    k_gemm_tc<HD, false, true, true, false><<<gemm_grid, 256, GEMM_DSMEM>>>(
        p_o1h, p_o1l, p_Wsth, p_Wstl, p_h2, nullptr, nullptr, b_skip, p_conv2, p_bnsum2, p_bnsq2);
    k_final<<<nb_node, 256>>>(out, gamma2, beta2);
}

// round 13
// speedup vs baseline: 1.3861x; 1.0407x over previous
#include <cuda_runtime.h>
#include <cuda_bf16.h>
#include <stdint.h>
#include <math.h>

// ---------------- problem constants ----------------
#define NN 50000
#define EE 800000
#define IND 256
#define HD 128
#define NHEADS 8
#define SCAN_BLK 256
#define NSCAN ((NN + SCAN_BLK - 1) / SCAN_BLK)   // 196
#define AK 24   // smem bf16 row stride (48B)
#define STG 12288
#define GEMM_DSMEM (2 * STG * 2)   // 49152 bytes
#define NEG_BIG (-1e30f)
#define NCONVA (NN * IND / 4 / 256)   // 12500 blocks for x conversion

// ---------------- scratch ----------------
__device__ __align__(16) __nv_bfloat16 g_xh[(size_t)NN * IND], g_xl[(size_t)NN * IND];
__device__ __align__(16) __nv_bfloat16 g_h0h[NN * HD], g_h0l[NN * HD];
__device__ __align__(16) __nv_bfloat16 g_o1h[NN * HD], g_o1l[NN * HD];
__device__ __align__(16) __nv_bfloat16 g_Winth[HD * IND], g_Wintl[HD * IND];
__device__ __align__(16) __nv_bfloat16 g_W1th[HD * HD], g_W1tl[HD * HD];
__device__ __align__(16) __nv_bfloat16 g_W2th[HD * HD], g_W2tl[HD * HD];
__device__ __align__(16) __nv_bfloat16 g_Wsth[HD * HD], g_Wstl[HD * HD];
__device__ __align__(16) float g_t1[NN * HD];
__device__ __align__(16) float g_t2[NN * HD];
__device__ __align__(16) float g_conv2[NN * HD];
__device__ __align__(16) float g_h2[NN * HD];
__device__ __align__(16) float g_as1[NN * NHEADS], g_ad1[NN * NHEADS];
__device__ __align__(16) float g_as2[NN], g_ad2[NN];
__device__ __align__(16) int   g_cnt[NN];
__device__ __align__(16) int   g_scantmp[NN];
__device__ __align__(16) int   g_blksum[SCAN_BLK];
__device__ __align__(16) int   g_rowptr[NN + 1];
__device__ __align__(16) int   g_cursor[NN];
__device__ __align__(16) int   g_csrc[EE];
__device__ __align__(16) float g_bnsum1[HD], g_bnsq1[HD], g_bnsum2[HD], g_bnsq2[HD];
__device__ __align__(16) float g_scale1[HD], g_shift1[HD];
__device__ __align__(16) float g_W1p[HD * HD], g_c1[HD];
__device__ int g_is64;

__device__ __forceinline__ float lrelu(float v) { return v >= 0.f ? v : 0.2f * v; }

__device__ __forceinline__ int edge_idx(const void* ei, long long pos) {
    if (g_is64) return (int)((const long long*)ei)[pos];
    return ((const int*)ei)[pos];
}

// ---------------- dtype detection (warp-parallel) ----------------
__global__ void k_detect(const void* ei) {
    const long long* q = (const long long*)ei;
    int lane = threadIdx.x;
    long long v0 = q[lane], v1 = q[lane + 32];
    int ok = (v0 >= 0 && v0 < NN && v1 >= 0 && v1 < NN);
    unsigned m = __ballot_sync(0xFFFFFFFFu, ok);
    if (lane == 0) g_is64 = (m == 0xFFFFFFFFu);
}

// ---------------- zero ----------------
__global__ void k_zero() {
    int i = blockIdx.x * blockDim.x + threadIdx.x;
    if (i < NN) g_cnt[i] = 0;
    if (i < HD) { g_bnsum1[i] = 0.f; g_bnsq1[i] = 0.f; g_bnsum2[i] = 0.f; g_bnsq2[i] = 0.f; }
}

// ---------------- CSR build ----------------
__global__ void k_count(const void* __restrict__ ei) {
    int e = blockIdx.x * blockDim.x + threadIdx.x;
    if (e < EE) {
        int d = edge_idx(ei, (long long)EE + e);
        if (d >= 0 && d < NN) atomicAdd(&g_cnt[d], 1);
    }
}

__global__ void k_scanA() {
    __shared__ int sh[SCAN_BLK];
    int tid = threadIdx.x;
    int i = blockIdx.x * SCAN_BLK + tid;
    int v = (i < NN) ? g_cnt[i] : 0;
    sh[tid] = v;
    __syncthreads();
#pragma unroll
    for (int off = 1; off < SCAN_BLK; off <<= 1) {
        int t = (tid >= off) ? sh[tid - off] : 0;
        __syncthreads();
        sh[tid] += t;
        __syncthreads();
    }
    if (i < NN) g_scantmp[i] = sh[tid];
    if (tid == SCAN_BLK - 1) g_blksum[blockIdx.x] = sh[tid];
}

// merged scanB+scanC: each block computes its own global offset from blksum
__global__ void k_scanC() {
    __shared__ int shp[8], sht[8];
    __shared__ int s_off, s_tot;
    int tid = threadIdx.x;
    int pv = (tid < NSCAN && tid < blockIdx.x) ? g_blksum[tid] : 0;   // prefix part
    int tv = (tid < NSCAN) ? g_blksum[tid] : 0;                        // total part
#pragma unroll
    for (int off = 16; off; off >>= 1) {
        pv += __shfl_xor_sync(0xFFFFFFFFu, pv, off);
        tv += __shfl_xor_sync(0xFFFFFFFFu, tv, off);
    }
    if ((tid & 31) == 0) { shp[tid >> 5] = pv; sht[tid >> 5] = tv; }
    __syncthreads();
    if (tid == 0) {
        int a = 0, b = 0;
#pragma unroll
        for (int k = 0; k < 8; k++) { a += shp[k]; b += sht[k]; }
        s_off = a; s_tot = b;
    }
    __syncthreads();
    int i = blockIdx.x * SCAN_BLK + tid;
    if (i < NN) {
        int r = s_off + g_scantmp[i] - g_cnt[i];
        g_rowptr[i] = r;
        g_cursor[i] = r;
    }
    if (blockIdx.x == NSCAN - 1 && tid == 0) g_rowptr[NN] = s_tot;
}

__global__ void k_fill(const void* __restrict__ ei) {
    int e = blockIdx.x * blockDim.x + threadIdx.x;
    if (e < EE) {
        int s = edge_idx(ei, e);
        int d = edge_idx(ei, (long long)EE + e);
        if (d >= 0 && d < NN && s >= 0 && s < NN) {
            int p = atomicAdd(&g_cursor[d], 1);
            if (p >= 0 && p < EE) g_csrc[p] = s;
        }
    }
}

// ---------------- merged conversion: x + W_in + W2 + W_skip ----------------
__device__ __forceinline__ void convW_row(const float* W, __nv_bfloat16* dh, __nv_bfloat16* dl,
                                          int n, int K, int tid, int nt) {
    for (int k = tid; k < K; k += nt) {
        float v = W[(size_t)k * HD + n];
        __nv_bfloat16 h = __float2bfloat16(v);
        dh[(size_t)n * K + k] = h;
        dl[(size_t)n * K + k] = __float2bfloat16(v - __bfloat162float(h));
    }
}

__global__ void k_conv_all(const float* __restrict__ x,
                           const float* __restrict__ Win,
                           const float* __restrict__ W2,
                           const float* __restrict__ Wskip) {
    int b = blockIdx.x, tid = threadIdx.x;
    if (b < NCONVA) {
        int i = b * 256 + tid;
        float4 v = *reinterpret_cast<const float4*>(x + (size_t)i * 4);
        __nv_bfloat16 h0 = __float2bfloat16(v.x), h1 = __float2bfloat16(v.y);
        __nv_bfloat16 h2 = __float2bfloat16(v.z), h3 = __float2bfloat16(v.w);
        __nv_bfloat162 ph0; ph0.x = h0; ph0.y = h1;
        __nv_bfloat162 ph1; ph1.x = h2; ph1.y = h3;
        __nv_bfloat162 pl0, pl1;
        pl0.x = __float2bfloat16(v.x - __bfloat162float(h0));
        pl0.y = __float2bfloat16(v.y - __bfloat162float(h1));
        pl1.x = __float2bfloat16(v.z - __bfloat162float(h2));
        pl1.y = __float2bfloat16(v.w - __bfloat162float(h3));
        *reinterpret_cast<__nv_bfloat162*>(g_xh + (size_t)i * 4) = ph0;
        *reinterpret_cast<__nv_bfloat162*>(g_xh + (size_t)i * 4 + 2) = ph1;
        *reinterpret_cast<__nv_bfloat162*>(g_xl + (size_t)i * 4) = pl0;
        *reinterpret_cast<__nv_bfloat162*>(g_xl + (size_t)i * 4 + 2) = pl1;
    } else if (b < NCONVA + HD) {
        convW_row(Win, g_Winth, g_Wintl, b - NCONVA, IND, tid, 256);
    } else if (b < NCONVA + 2 * HD) {
        convW_row(W2, g_W2th, g_W2tl, b - NCONVA - HD, HD, tid, 256);
    } else {
        convW_row(Wskip, g_Wsth, g_Wstl, b - NCONVA - 2 * HD, HD, tid, 256);
    }
}

__global__ void k_convW(const float* __restrict__ W, __nv_bfloat16* __restrict__ dh,
                        __nv_bfloat16* __restrict__ dl, int K) {
    int n = blockIdx.x;
    for (int k = threadIdx.x; k < K; k += blockDim.x) {
        float v = W[(size_t)k * HD + n];
        __nv_bfloat16 h = __float2bfloat16(v);
        dh[(size_t)n * K + k] = h;
        dl[(size_t)n * K + k] = __float2bfloat16(v - __bfloat162float(h));
    }
}

// ---------------- split-bf16 tensor-core GEMM (double-buffered, optional fused att) ----------------
__device__ __forceinline__ void mma16816(float* c, const uint32_t* a, uint32_t b0, uint32_t b1) {
    asm volatile(
        "mma.sync.aligned.m16n8k16.row.col.f32.bf16.bf16.f32 "
        "{%0,%1,%2,%3}, {%4,%5,%6,%7}, {%8,%9}, {%0,%1,%2,%3};"
        : "+f"(c[0]), "+f"(c[1]), "+f"(c[2]), "+f"(c[3])
        : "r"(a[0]), "r"(a[1]), "r"(a[2]), "r"(a[3]), "r"(b0), "r"(b1));
}

// ATT1: fused per-head attention dot products (conv1, 8 heads) -> g_as1/g_ad1
// ATT2: fused single-head attention dots (conv2) -> g_as2/g_ad2
template <int K, bool LEAKY, bool ADDM, bool STATS, bool OUTBF, bool ATT1, bool ATT2>
__global__ void __launch_bounds__(256, 2) k_gemm_tc(
        const __nv_bfloat16* __restrict__ Ahg, const __nv_bfloat16* __restrict__ Alg,
        const __nv_bfloat16* __restrict__ Bhg, const __nv_bfloat16* __restrict__ Blg,
        float* __restrict__ C, __nv_bfloat16* __restrict__ Ch, __nv_bfloat16* __restrict__ Cl,
        const float* __restrict__ bias, const float* __restrict__ addm,
        float* __restrict__ bnsum, float* __restrict__ bnsq,
        const float* __restrict__ attS, const float* __restrict__ attD) {
    extern __shared__ __nv_bfloat16 dyn[];
    __shared__ float s_sum[128], s_sq[128];
    __shared__ float s_as[128], s_ad[128];
    const int tid = threadIdx.x;
    const int m0 = blockIdx.x * 128;
    if (STATS && tid < 128) { s_sum[tid] = 0.f; s_sq[tid] = 0.f; }
    if (ATT2 && tid < 128) { s_as[tid] = 0.f; s_ad[tid] = 0.f; }
    const int lane = tid & 31;
    const int wid = tid >> 5;
    const int g = lane >> 2, r = lane & 3;
    const int wm = (wid & 3) * 32;
    const int wn = (wid >> 2) * 64;

    float acc[2][8][4];
#pragma unroll
    for (int i = 0; i < 2; i++)
#pragma unroll
        for (int j = 0; j < 8; j++)
#pragma unroll
            for (int q = 0; q < 4; q++) acc[i][j][q] = 0.f;

    const int row = tid >> 1;
    const int koff = (tid & 1) * 8;
    const bool arow_ok = (m0 + row) < NN;
    const size_t abase = (size_t)(m0 + row) * K;
    const size_t bbase = (size_t)row * K;

    uint4 rah, ral, rbh, rbl;
    const uint4 z4 = make_uint4(0, 0, 0, 0);

    rah = arow_ok ? *reinterpret_cast<const uint4*>(Ahg + abase + koff) : z4;
    ral = arow_ok ? *reinterpret_cast<const uint4*>(Alg + abase + koff) : z4;
    rbh = *reinterpret_cast<const uint4*>(Bhg + bbase + koff);
    rbl = *reinterpret_cast<const uint4*>(Blg + bbase + koff);
    {
        __nv_bfloat16* st = dyn;
        *reinterpret_cast<uint4*>(&st[row * AK + koff])        = rah;
        *reinterpret_cast<uint4*>(&st[3072 + row * AK + koff]) = ral;
        *reinterpret_cast<uint4*>(&st[6144 + row * AK + koff]) = rbh;
        *reinterpret_cast<uint4*>(&st[9216 + row * AK + koff]) = rbl;
    }
    __syncthreads();

    constexpr int NC = K / 16;
#pragma unroll 2
    for (int c = 0; c < NC; c++) {
        const int cur = c & 1;
        __nv_bfloat16* Ahs = dyn + cur * STG;
        __nv_bfloat16* Als = Ahs + 3072;
        __nv_bfloat16* Bhs = Ahs + 6144;
        __nv_bfloat16* Bls = Ahs + 9216;
        const bool more = (c + 1 < NC);
        if (more) {
            int k0 = (c + 1) * 16;
            rah = arow_ok ? *reinterpret_cast<const uint4*>(Ahg + abase + k0 + koff) : z4;
            ral = arow_ok ? *reinterpret_cast<const uint4*>(Alg + abase + k0 + koff) : z4;
            rbh = *reinterpret_cast<const uint4*>(Bhg + bbase + k0 + koff);
            rbl = *reinterpret_cast<const uint4*>(Blg + bbase + k0 + koff);
        }
        uint32_t ah[2][4], al[2][4];
#pragma unroll
        for (int mi = 0; mi < 2; mi++) {
            int mr = wm + mi * 16;
            ah[mi][0] = *(const uint32_t*)&Ahs[(mr + g) * AK + 2 * r];
            ah[mi][1] = *(const uint32_t*)&Ahs[(mr + g + 8) * AK + 2 * r];
            ah[mi][2] = *(const uint32_t*)&Ahs[(mr + g) * AK + 2 * r + 8];
            ah[mi][3] = *(const uint32_t*)&Ahs[(mr + g + 8) * AK + 2 * r + 8];
            al[mi][0] = *(const uint32_t*)&Als[(mr + g) * AK + 2 * r];
            al[mi][1] = *(const uint32_t*)&Als[(mr + g + 8) * AK + 2 * r];
            al[mi][2] = *(const uint32_t*)&Als[(mr + g) * AK + 2 * r + 8];
            al[mi][3] = *(const uint32_t*)&Als[(mr + g + 8) * AK + 2 * r + 8];
        }
#pragma unroll
        for (int ni = 0; ni < 8; ni++) {
            int nr = (wn + ni * 8 + g) * AK;
            uint32_t bh0 = *(const uint32_t*)&Bhs[nr + 2 * r];
            uint32_t bh1 = *(const uint32_t*)&Bhs[nr + 2 * r + 8];
            uint32_t bl0 = *(const uint32_t*)&Bls[nr + 2 * r];
            uint32_t bl1 = *(const uint32_t*)&Bls[nr + 2 * r + 8];
#pragma unroll
            for (int mi = 0; mi < 2; mi++) {
                mma16816(acc[mi][ni], al[mi], bh0, bh1);
                mma16816(acc[mi][ni], ah[mi], bl0, bl1);
                mma16816(acc[mi][ni], ah[mi], bh0, bh1);
            }
        }
        if (more) {
            __nv_bfloat16* st = dyn + (cur ^ 1) * STG;
            *reinterpret_cast<uint4*>(&st[row * AK + koff])        = rah;
            *reinterpret_cast<uint4*>(&st[3072 + row * AK + koff]) = ral;
            *reinterpret_cast<uint4*>(&st[6144 + row * AK + koff]) = rbh;
            *reinterpret_cast<uint4*>(&st[9216 + row * AK + koff]) = rbl;
        }
        __syncthreads();
    }

    // ---- epilogue ----
#pragma unroll
    for (int mi = 0; mi < 2; mi++) {
        // per-mi attention accumulators: [AB row][local head]
        float sa[2][4], da[2][4];
        if (ATT1 || ATT2) {
#pragma unroll
            for (int ab = 0; ab < 2; ab++)
#pragma unroll
                for (int lh = 0; lh < 4; lh++) { sa[ab][lh] = 0.f; da[ab][lh] = 0.f; }
        }
#pragma unroll
        for (int ni = 0; ni < 8; ni++) {
            int mA = m0 + wm + mi * 16 + g;
            int mB = mA + 8;
            int n = wn + ni * 8 + 2 * r;
            float bc0 = bias ? bias[n] : 0.f;
            float bc1 = bias ? bias[n + 1] : 0.f;
            float v0 = acc[mi][ni][0] + bc0, v1 = acc[mi][ni][1] + bc1;
            float v2 = acc[mi][ni][2] + bc0, v3 = acc[mi][ni][3] + bc1;
            bool okA = mA < NN, okB = mB < NN;
            if (ATT1 || ATT2) {
                float as0 = attS[n], as1 = attS[n + 1];
                float ad0 = attD[n], ad1 = attD[n + 1];
                int lh = ATT1 ? (ni >> 1) : 0;
                sa[0][lh] += v0 * as0 + v1 * as1;
                sa[1][lh] += v2 * as0 + v3 * as1;
                da[0][lh] += v0 * ad0 + v1 * ad1;
                da[1][lh] += v2 * ad0 + v3 * ad1;
            }
            if (okA) {
                if (ADDM) { v0 += addm[(size_t)mA * HD + n]; v1 += addm[(size_t)mA * HD + n + 1]; }
                if (LEAKY) { v0 = lrelu(v0); v1 = lrelu(v1); }
                if (OUTBF) {
                    __nv_bfloat16 h0 = __float2bfloat16(v0), h1 = __float2bfloat16(v1);
                    __nv_bfloat162 ph; ph.x = h0; ph.y = h1;
                    __nv_bfloat162 pl;
                    pl.x = __float2bfloat16(v0 - __bfloat162float(h0));
                    pl.y = __float2bfloat16(v1 - __bfloat162float(h1));
                    *reinterpret_cast<__nv_bfloat162*>(Ch + (size_t)mA * HD + n) = ph;
                    *reinterpret_cast<__nv_bfloat162*>(Cl + (size_t)mA * HD + n) = pl;
                } else {
                    *(float2*)&C[(size_t)mA * HD + n] = make_float2(v0, v1);
                }
            }
            if (okB) {
                if (ADDM) { v2 += addm[(size_t)mB * HD + n]; v3 += addm[(size_t)mB * HD + n + 1]; }
                if (LEAKY) { v2 = lrelu(v2); v3 = lrelu(v3); }
                if (OUTBF) {
                    __nv_bfloat16 h2 = __float2bfloat16(v2), h3 = __float2bfloat16(v3);
                    __nv_bfloat162 ph; ph.x = h2; ph.y = h3;
                    __nv_bfloat162 pl;
                    pl.x = __float2bfloat16(v2 - __bfloat162float(h2));
                    pl.y = __float2bfloat16(v3 - __bfloat162float(h3));
                    *reinterpret_cast<__nv_bfloat162*>(Ch + (size_t)mB * HD + n) = ph;
                    *reinterpret_cast<__nv_bfloat162*>(Cl + (size_t)mB * HD + n) = pl;
                } else {
                    *(float2*)&C[(size_t)mB * HD + n] = make_float2(v2, v3);
                }
            }
            if (STATS && (okA || okB)) {
                float s0 = (okA ? v0 : 0.f) + (okB ? v2 : 0.f);
                float s1 = (okA ? v1 : 0.f) + (okB ? v3 : 0.f);
                float q0 = (okA ? v0 * v0 : 0.f) + (okB ? v2 * v2 : 0.f);
                float q1 = (okA ? v1 * v1 : 0.f) + (okB ? v3 * v3 : 0.f);
                atomicAdd(&s_sum[n], s0);
                atomicAdd(&s_sum[n + 1], s1);
                atomicAdd(&s_sq[n], q0);
                atomicAdd(&s_sq[n + 1], q1);
            }
        }
        if (ATT1 || ATT2) {
            // quad reduce over r (covers the 16 cols of each head / all 64 warp cols)
#pragma unroll
            for (int ab = 0; ab < 2; ab++)
#pragma unroll
                for (int lh = 0; lh < 4; lh++) {
                    sa[ab][lh] += __shfl_xor_sync(0xFFFFFFFFu, sa[ab][lh], 1);
                    sa[ab][lh] += __shfl_xor_sync(0xFFFFFFFFu, sa[ab][lh], 2);
                    da[ab][lh] += __shfl_xor_sync(0xFFFFFFFFu, da[ab][lh], 1);
                    da[ab][lh] += __shfl_xor_sync(0xFFFFFFFFu, da[ab][lh], 2);
                }
            if (r == 0) {
#pragma unroll
                for (int ab = 0; ab < 2; ab++) {
                    int m = m0 + wm + mi * 16 + g + ab * 8;
                    if (m < NN) {
                        if (ATT1) {
                            // heads (wn>>4)..(wn>>4)+3 — disjoint per warp n-group: plain stores
                            float4 vs = make_float4(sa[ab][0], sa[ab][1], sa[ab][2], sa[ab][3]);
                            float4 vd = make_float4(da[ab][0], da[ab][1], da[ab][2], da[ab][3]);
                            *reinterpret_cast<float4*>(g_as1 + (size_t)m * NHEADS + (wn >> 4)) = vs;
                            *reinterpret_cast<float4*>(g_ad1 + (size_t)m * NHEADS + (wn >> 4)) = vd;
                        } else {
                            // single head: two warp n-groups collide -> smem atomic
                            atomicAdd(&s_as[wm + mi * 16 + g + ab * 8], sa[ab][0]);
                            atomicAdd(&s_ad[wm + mi * 16 + g + ab * 8], da[ab][0]);
                        }
                    }
                }
            }
        }
    }
    if (STATS) {
        __syncthreads();
        if (tid < 128) {
            atomicAdd(&bnsum[tid], s_sum[tid]);
            atomicAdd(&bnsq[tid], s_sq[tid]);
        }
    }
    if (ATT2) {
        __syncthreads();
        if (tid < 128 && m0 + tid < NN) {
            g_as2[m0 + tid] = s_as[tid];
            g_ad2[m0 + tid] = s_ad[tid];
        }
    }
}

// ---------------- BN1 prep ----------------
__global__ void k_bnprep1(const float* __restrict__ gamma1, const float* __restrict__ beta1,
                          const float* __restrict__ W1) {
    int c = threadIdx.x;
    float mean = g_bnsum1[c] / (float)NN;
    float var = g_bnsq1[c] / (float)NN - mean * mean;
    float sc = gamma1[c] * rsqrtf(var + 1e-5f);
    float sh = beta1[c] - mean * sc;
    g_scale1[c] = sc;
    g_shift1[c] = sh;
    __syncthreads();
    float cj = 0.f;
    for (int k = 0; k < HD; k++) {
        cj += g_shift1[k] * W1[k * HD + c];
        g_W1p[k * HD + c] = g_scale1[k] * W1[k * HD + c];
    }
    g_c1[c] = cj;
}

// online-softmax combine (NaN-free with finite sentinel)
__device__ __forceinline__ void sm_merge(float& mx, float& den, float omx, float oden) {
    float nm = fmaxf(mx, omx);
    den = den * __expf(mx - nm) + oden * __expf(omx - nm);
    mx = nm;
}

// ---------------- fused softmax + aggregation, conv1 ----------------
__global__ void k_sagg1(const float* __restrict__ bias1) {
    int gt = blockIdx.x * blockDim.x + threadIdx.x;
    int w = gt >> 5, lane = gt & 31;
    if (w >= NN) return;
    int beg = g_rowptr[w], end = g_rowptr[w + 1];

    int h8 = lane & 7, es = lane >> 3;
    float ad8 = g_ad1[w * NHEADS + h8];
    float mx = NEG_BIG, den = 0.f;
    for (int j = beg + es; j < end; j += 4) {
        int s = g_csrc[j];
        float v = lrelu(g_as1[s * NHEADS + h8] + ad8);
        float nm = fmaxf(mx, v);
        den = den * __expf(mx - nm) + __expf(v - nm);
        mx = nm;
    }
    sm_merge(mx, den, __shfl_xor_sync(0xFFFFFFFFu, mx, 8),  __shfl_xor_sync(0xFFFFFFFFu, den, 8));
    sm_merge(mx, den, __shfl_xor_sync(0xFFFFFFFFu, mx, 16), __shfl_xor_sync(0xFFFFFFFFu, den, 16));
    float inv = 1.f / fmaxf(den, 1e-16f);

    int hh = lane >> 2;
    float mxh  = __shfl_sync(0xFFFFFFFFu, mx, hh);
    float invh = __shfl_sync(0xFFFFFFFFu, inv, hh);
    float adh  = __shfl_sync(0xFFFFFFFFu, ad8, hh);

    float ax = 0.f, ay = 0.f, az = 0.f, aw = 0.f;
#pragma unroll 2
    for (int j = beg; j < end; j++) {
        int s = g_csrc[j];
        float a = __expf(lrelu(g_as1[s * NHEADS + hh] + adh) - mxh) * invh;
        float4 t4 = *reinterpret_cast<const float4*>(g_t1 + (size_t)s * HD + lane * 4);
        ax += a * t4.x; ay += a * t4.y; az += a * t4.z; aw += a * t4.w;
    }
    float4 b4 = *reinterpret_cast<const float4*>(bias1 + lane * 4);
    float v0 = lrelu(ax + b4.x), v1 = lrelu(ay + b4.y);
    float v2 = lrelu(az + b4.z), v3 = lrelu(aw + b4.w);
    size_t base = (size_t)w * HD + lane * 4;
    __nv_bfloat16 h0 = __float2bfloat16(v0), h1 = __float2bfloat16(v1);
    __nv_bfloat16 h2 = __float2bfloat16(v2), h3 = __float2bfloat16(v3);
    __nv_bfloat162 ph0; ph0.x = h0; ph0.y = h1;
    __nv_bfloat162 ph1; ph1.x = h2; ph1.y = h3;
    __nv_bfloat162 pl0, pl1;
    pl0.x = __float2bfloat16(v0 - __bfloat162float(h0));
    pl0.y = __float2bfloat16(v1 - __bfloat162float(h1));
    pl1.x = __float2bfloat16(v2 - __bfloat162float(h2));
    pl1.y = __float2bfloat16(v3 - __bfloat162float(h3));
    *reinterpret_cast<__nv_bfloat162*>(g_o1h + base) = ph0;
    *reinterpret_cast<__nv_bfloat162*>(g_o1h + base + 2) = ph1;
    *reinterpret_cast<__nv_bfloat162*>(g_o1l + base) = pl0;
    *reinterpret_cast<__nv_bfloat162*>(g_o1l + base + 2) = pl1;
}

// ---------------- fused softmax + aggregation, conv2 ----------------
__global__ void k_sagg2(const float* __restrict__ bias2) {
    int gt = blockIdx.x * blockDim.x + threadIdx.x;
    int w = gt >> 5, lane = gt & 31;
    if (w >= NN) return;
    int beg = g_rowptr[w], end = g_rowptr[w + 1];
    float ad = g_ad2[w];
    float mx = NEG_BIG, den = 0.f;
    for (int j = beg + lane; j < end; j += 32) {
        float v = lrelu(g_as2[g_csrc[j]] + ad);
        float nm = fmaxf(mx, v);
        den = den * __expf(mx - nm) + __expf(v - nm);
        mx = nm;
    }
#pragma unroll
    for (int off = 16; off; off >>= 1)
        sm_merge(mx, den, __shfl_xor_sync(0xFFFFFFFFu, mx, off), __shfl_xor_sync(0xFFFFFFFFu, den, off));
    float inv = 1.f / fmaxf(den, 1e-16f);

    float ax = 0.f, ay = 0.f, az = 0.f, aw = 0.f;
#pragma unroll 2
    for (int j = beg; j < end; j++) {
        int s = g_csrc[j];
        float a = __expf(lrelu(g_as2[s] + ad) - mx) * inv;
        float4 t4 = *reinterpret_cast<const float4*>(g_t2 + (size_t)s * HD + lane * 4);
        ax += a * t4.x; ay += a * t4.y; az += a * t4.z; aw += a * t4.w;
    }
    float4 b4 = *reinterpret_cast<const float4*>(bias2 + lane * 4);
    float4 o = make_float4(ax + b4.x, ay + b4.y, az + b4.z, aw + b4.w);
    *reinterpret_cast<float4*>(g_conv2 + (size_t)w * HD + lane * 4) = o;
}

// ---------------- final: BN2 (inline) + row L2 normalize ----------------
__global__ void k_final(float* __restrict__ out, const float* __restrict__ gamma2,
                        const float* __restrict__ beta2) {
    int gt = blockIdx.x * blockDim.x + threadIdx.x;
    int w = gt >> 5, lane = gt & 31;
    if (w >= NN) return;
    int c = lane * 4;
    float4 sum4 = *reinterpret_cast<const float4*>(g_bnsum2 + c);
    float4 sq4  = *reinterpret_cast<const float4*>(g_bnsq2 + c);
    float4 gm4  = *reinterpret_cast<const float4*>(gamma2 + c);
    float4 bt4  = *reinterpret_cast<const float4*>(beta2 + c);
    const float invN = 1.f / (float)NN;
    float m0 = sum4.x * invN, m1 = sum4.y * invN, m2 = sum4.z * invN, m3 = sum4.w * invN;
    float sc0 = gm4.x * rsqrtf(sq4.x * invN - m0 * m0 + 1e-5f);
    float sc1 = gm4.y * rsqrtf(sq4.y * invN - m1 * m1 + 1e-5f);
    float sc2 = gm4.z * rsqrtf(sq4.z * invN - m2 * m2 + 1e-5f);
    float sc3 = gm4.w * rsqrtf(sq4.w * invN - m3 * m3 + 1e-5f);
    float sh0 = bt4.x - m0 * sc0, sh1 = bt4.y - m1 * sc1;
    float sh2 = bt4.z - m2 * sc2, sh3 = bt4.w - m3 * sc3;

    float4 h4 = *reinterpret_cast<const float4*>(g_h2 + (size_t)w * HD + c);
    float4 y;
    y.x = h4.x * sc0 + sh0; y.y = h4.y * sc1 + sh1;
    y.z = h4.z * sc2 + sh2; y.w = h4.w * sc3 + sh3;
    float ss = y.x * y.x + y.y * y.y + y.z * y.z + y.w * y.w;
#pragma unroll
    for (int off = 16; off; off >>= 1) ss += __shfl_xor_sync(0xFFFFFFFFu, ss, off);
    float inv = 1.f / fmaxf(sqrtf(ss), 1e-12f);
    y.x *= inv; y.y *= inv; y.z *= inv; y.w *= inv;
    *reinterpret_cast<float4*>(out + (size_t)w * HD + c) = y;
}

// ---------------- host launcher ----------------
extern "C" void kernel_launch(void* const* d_in, const int* in_sizes, int n_in,
                              void* d_out, int out_size) {
    const float* x        = (const float*)d_in[0];
    const float* W_in     = (const float*)d_in[1];
    const float* b_in     = (const float*)d_in[2];
    const float* gamma1   = (const float*)d_in[3];
    const float* beta1    = (const float*)d_in[4];
    const float* W1       = (const float*)d_in[5];
    const float* att_src1 = (const float*)d_in[6];
    const float* att_dst1 = (const float*)d_in[7];
    const float* bias1    = (const float*)d_in[8];
    const float* W2       = (const float*)d_in[9];
    const float* att_src2 = (const float*)d_in[10];
    const float* att_dst2 = (const float*)d_in[11];
    const float* bias2    = (const float*)d_in[12];
    const float* W_skip   = (const float*)d_in[13];
    const float* b_skip   = (const float*)d_in[14];
    const float* gamma2   = (const float*)d_in[15];
    const float* beta2    = (const float*)d_in[16];
    const void*  ei       = (const void*)d_in[17];
    float* out = (float*)d_out;

    __nv_bfloat16 *p_xh, *p_xl, *p_h0h, *p_h0l, *p_o1h, *p_o1l;
    __nv_bfloat16 *p_Winth, *p_Wintl, *p_W1th, *p_W1tl, *p_W2th, *p_W2tl, *p_Wsth, *p_Wstl;
    float *p_t1, *p_t2, *p_conv2, *p_h2, *p_W1p, *p_c1;
    float *p_bnsum1, *p_bnsq1, *p_bnsum2, *p_bnsq2;
    cudaGetSymbolAddress((void**)&p_xh, g_xh);
    cudaGetSymbolAddress((void**)&p_xl, g_xl);
    cudaGetSymbolAddress((void**)&p_h0h, g_h0h);
    cudaGetSymbolAddress((void**)&p_h0l, g_h0l);
    cudaGetSymbolAddress((void**)&p_o1h, g_o1h);
    cudaGetSymbolAddress((void**)&p_o1l, g_o1l);
    cudaGetSymbolAddress((void**)&p_Winth, g_Winth);
    cudaGetSymbolAddress((void**)&p_Wintl, g_Wintl);
    cudaGetSymbolAddress((void**)&p_W1th, g_W1th);
    cudaGetSymbolAddress((void**)&p_W1tl, g_W1tl);
    cudaGetSymbolAddress((void**)&p_W2th, g_W2th);
    cudaGetSymbolAddress((void**)&p_W2tl, g_W2tl);
    cudaGetSymbolAddress((void**)&p_Wsth, g_Wsth);
    cudaGetSymbolAddress((void**)&p_Wstl, g_Wstl);
    cudaGetSymbolAddress((void**)&p_t1, g_t1);
    cudaGetSymbolAddress((void**)&p_t2, g_t2);
    cudaGetSymbolAddress((void**)&p_conv2, g_conv2);
    cudaGetSymbolAddress((void**)&p_h2, g_h2);
    cudaGetSymbolAddress((void**)&p_W1p, g_W1p);
    cudaGetSymbolAddress((void**)&p_c1, g_c1);
    cudaGetSymbolAddress((void**)&p_bnsum1, g_bnsum1);
    cudaGetSymbolAddress((void**)&p_bnsq1, g_bnsq1);
    cudaGetSymbolAddress((void**)&p_bnsum2, g_bnsum2);
    cudaGetSymbolAddress((void**)&p_bnsq2, g_bnsq2);

    cudaFuncSetAttribute(k_gemm_tc<IND, true, false, true, true, false, false>,
                         cudaFuncAttributeMaxDynamicSharedMemorySize, GEMM_DSMEM);
    cudaFuncSetAttribute(k_gemm_tc<HD, false, false, false, false, true, false>,
                         cudaFuncAttributeMaxDynamicSharedMemorySize, GEMM_DSMEM);
    cudaFuncSetAttribute(k_gemm_tc<HD, false, false, false, false, false, true>,
                         cudaFuncAttributeMaxDynamicSharedMemorySize, GEMM_DSMEM);
    cudaFuncSetAttribute(k_gemm_tc<HD, false, true, true, false, false, false>,
                         cudaFuncAttributeMaxDynamicSharedMemorySize, GEMM_DSMEM);

    const int nb_edge = (EE + 255) / 256;
    const int nb_node = (NN * 32 + 255) / 256;
    const int gemm_grid = (NN + 127) / 128;

    // GEMM1 early (CSR-independent) so the profiler window captures it
    k_conv_all<<<NCONVA + 3 * HD, 256>>>(x, W_in, W2, W_skip);
    k_zero<<<(NN + 255) / 256, 256>>>();
    k_gemm_tc<IND, true, false, true, true, false, false><<<gemm_grid, 256, GEMM_DSMEM>>>(
        p_xh, p_xl, p_Winth, p_Wintl, nullptr, p_h0h, p_h0l, b_in, nullptr,
        p_bnsum1, p_bnsq1, nullptr, nullptr);

    k_detect<<<1, 32>>>(ei);
    k_count<<<nb_edge, 256>>>(ei);
    k_scanA<<<NSCAN, SCAN_BLK>>>();
    k_scanC<<<NSCAN, SCAN_BLK>>>();
    k_fill<<<nb_edge, 256>>>(ei);

    k_bnprep1<<<1, HD>>>(gamma1, beta1, W1);
    k_convW<<<HD, 256>>>(p_W1p, p_W1th, p_W1tl, HD);
    // GEMM2: t1 = h0 @ W1p + c1, fused per-head att dots
    k_gemm_tc<HD, false, false, false, false, true, false><<<gemm_grid, 256, GEMM_DSMEM>>>(
        p_h0h, p_h0l, p_W1th, p_W1tl, p_t1, nullptr, nullptr, p_c1, nullptr,
        nullptr, nullptr, att_src1, att_dst1);
    k_sagg1<<<nb_node, 256>>>(bias1);
    // GEMM3: t2 = out1 @ W2, fused single-head att dots
    k_gemm_tc<HD, false, false, false, false, false, true><<<gemm_grid, 256, GEMM_DSMEM>>>(
        p_o1h, p_o1l, p_W2th, p_W2tl, p_t2, nullptr, nullptr, nullptr, nullptr,
        nullptr, nullptr, att_src2, att_dst2);
    k_sagg2<<<nb_node, 256>>>(bias2);
    // GEMM4: h2 = conv2 + out1 @ W_skip + b_skip, BN2 stats
    k_gemm_tc<HD, false, true, true, false, false, false><<<gemm_grid, 256, GEMM_DSMEM>>>(
        p_o1h, p_o1l, p_Wsth, p_Wstl, p_h2, nullptr, nullptr, b_skip, p_conv2,
        p_bnsum2, p_bnsq2, nullptr, nullptr);
    k_final<<<nb_node, 256>>>(out, gamma2, beta2);
}